// round 3
// baseline (speedup 1.0000x reference)
#include <cuda_runtime.h>
#include <math.h>

#define NN 8192
#define HH 128
#define H3 384
#define EPSF 1e-6f
#define PMF 0.9999f

// ----------------------------- scratch -----------------------------
__device__ float g_l1[NN*HH], g_l2[NN*HH], g_lc1[NN*HH], g_lc2[NN*HH];
__device__ float g_Yq[NN*HH];
__device__ float g_Yup1[NN*HH], g_Yup2[NN*HH], g_Yup3[NN*HH];
__device__ float g_Yuf1[NN*HH], g_Yuf2[NN*HH], g_Yuf3[NN*HH];
__device__ float g_Ywc1[NN*HH], g_Ywc2[NN*HH], g_Ywc3[NN*HH];
__device__ float g_x1p[NN*HH], g_x1s[NN*HH];
__device__ float g_h1p[NN*HH], g_h1s[NN*HH], g_h1e[NN*HH];
__device__ float g_P1[NN*HH], g_P2[NN*HH], g_E3[NN*HH];
__device__ float g_A1[NN*HH], g_A2[NN*HH], g_A3[NN*HH];
__device__ float g_c1o[NN*HH], g_c2o[NN*HH], g_c3o[NN*HH];
__device__ float g_lamHp[NN], g_lamHs[NN], g_lam1[NN], g_lam2[NN];
__device__ float g_Z1[NN*H3], g_Z2[NN*H3], g_Z3[NN*H3];

// ----------------------------- helpers -----------------------------
__device__ __forceinline__ float wred(float s){
  #pragma unroll
  for(int o=16;o;o>>=1) s += __shfl_xor_sync(0xffffffffu, s, o);
  return s;
}
template<int R> __device__ __forceinline__ float wdot(const float* a, const float* b){
  float s=0.f;
  #pragma unroll
  for(int i=0;i<R;i++) s += a[i]*b[i];
  return wred(s);
}
template<int R> __device__ __forceinline__ float wnrm(const float* a){
  return sqrtf(wdot<R>(a,a) + 1e-15f);
}
__device__ __forceinline__ float atanh_c(float u){
  u = fminf(fmaxf(u, -1.0f+1e-5f), 1.0f-1e-5f);
  return atanhf(u);
}
__device__ __forceinline__ float tan_c(float u){
  u = fminf(fmaxf(u, -1.47079f), 1.47079f);
  return tanf(u);
}
__device__ __forceinline__ float safe_den(float d){
  return d >= 0.f ? fmaxf(d, EPSF) : fminf(d, -EPSF);
}
__device__ __forceinline__ void ld4(float* v, const float* p){
  float4 t = *(const float4*)p; v[0]=t.x; v[1]=t.y; v[2]=t.z; v[3]=t.w;
}
__device__ __forceinline__ void st4(float* p, const float* v){
  *(float4*)p = make_float4(v[0],v[1],v[2],v[3]);
}
__device__ __forceinline__ void cp4(float* d, const float* s){
  #pragma unroll
  for(int i=0;i<4;i++) d[i]=s[i];
}
template<int R> __device__ __forceinline__ void sigm(float* v){
  #pragma unroll
  for(int i=0;i<R;i++) v[i] = 1.f/(1.f+expf(-v[i]));
}
template<int R> __device__ __forceinline__ void tanhv(float* v){
  #pragma unroll
  for(int i=0;i<R;i++) v[i] = tanhf(v[i]);
}
template<int R> __device__ __forceinline__ void proj_p(float* v){
  float n = wnrm<R>(v);
  if(n > PMF){
    float s = PMF/n;
    #pragma unroll
    for(int i=0;i<R;i++) v[i]*=s;
  }
}
template<int R> __device__ __forceinline__ void expmap0_p(float* v){
  float n = wnrm<R>(v); float s = tanhf(n)/n;
  #pragma unroll
  for(int i=0;i<R;i++) v[i]*=s;
  proj_p<R>(v);
}
template<int R> __device__ __forceinline__ void logmap0_p(float* v){
  float n = wnrm<R>(v); float s = atanh_c(n)/n;
  #pragma unroll
  for(int i=0;i<R;i++) v[i]*=s;
}
template<int R> __device__ __forceinline__ void expmap0_s(float* v){
  float n = wnrm<R>(v); float s = tan_c(n)/n;
  #pragma unroll
  for(int i=0;i<R;i++) v[i]*=s;
}
template<int R> __device__ __forceinline__ void logmap0_s(float* v){
  float n = wnrm<R>(v); float s = atanf(n)/n;
  #pragma unroll
  for(int i=0;i<R;i++) v[i]*=s;
}
template<int R> __device__ __forceinline__ void smul_p(float r, float* v){
  float n = wnrm<R>(v); float s = tanhf(r*atanh_c(n))/n;
  #pragma unroll
  for(int i=0;i<R;i++) v[i]*=s;
  proj_p<R>(v);
}
template<int R> __device__ __forceinline__ void smul_s(float r, float* v){
  float n = wnrm<R>(v); float s = tan_c(r*atanf(n))/n;
  #pragma unroll
  for(int i=0;i<R;i++) v[i]*=s;
}
template<int R> __device__ __forceinline__ void madd_p(const float* x, const float* y, float* o){
  float x2 = wdot<R>(x,x), y2 = wdot<R>(y,y), xy = wdot<R>(x,y);
  float cx = 1.f + 2.f*xy + y2;
  float cy = 1.f - x2;
  float dn = safe_den(1.f + 2.f*xy + x2*y2);
  #pragma unroll
  for(int i=0;i<R;i++) o[i] = (cx*x[i] + cy*y[i])/dn;
  proj_p<R>(o);
}
template<int R> __device__ __forceinline__ void madd_s(const float* x, const float* y, float* o){
  float x2 = wdot<R>(x,x), y2 = wdot<R>(y,y), xy = wdot<R>(x,y);
  float cx = 1.f - 2.f*xy - y2;
  float cy = 1.f + x2;
  float dn = safe_den(1.f - 2.f*xy + x2*y2);
  #pragma unroll
  for(int i=0;i<R;i++) o[i] = (cx*x[i] + cy*y[i])/dn;
}
template<int R> __device__ __forceinline__ void pwmul_p(const float* w, const float* x, float* o){
  float wx[R];
  #pragma unroll
  for(int i=0;i<R;i++) wx[i] = w[i]*x[i];
  float nx = wnrm<R>(x), nwx = wnrm<R>(wx);
  float s = tanhf(nwx/nx*atanh_c(nx))/nwx;
  #pragma unroll
  for(int i=0;i<R;i++) o[i] = wx[i]*s;
  proj_p<R>(o);
}
template<int R> __device__ __forceinline__ void pwmul_s(const float* w, const float* x, float* o){
  float wx[R];
  #pragma unroll
  for(int i=0;i<R;i++) wx[i] = w[i]*x[i];
  float nx = wnrm<R>(x), nwx = wnrm<R>(wx);
  float s = tan_c(nwx/nx*atanf(nx))/nwx;
  #pragma unroll
  for(int i=0;i<R;i++) o[i] = wx[i]*s;
}
template<int R> __device__ __forceinline__ void pwmulg_p(const float* w, float g, float* o){
  float wx[R];
  #pragma unroll
  for(int i=0;i<R;i++) wx[i] = w[i]*g;
  float nx = sqrtf(g*g + 1e-15f), nwx = wnrm<R>(wx);
  float s = tanhf(nwx/nx*atanh_c(nx))/nwx;
  #pragma unroll
  for(int i=0;i<R;i++) o[i] = wx[i]*s;
  proj_p<R>(o);
}
template<int R> __device__ __forceinline__ void pwmulg_s(const float* w, float g, float* o){
  float wx[R];
  #pragma unroll
  for(int i=0;i<R;i++) wx[i] = w[i]*g;
  float nx = sqrtf(g*g + 1e-15f), nwx = wnrm<R>(wx);
  float s = tan_c(nwx/nx*atanf(nx))/nwx;
  #pragma unroll
  for(int i=0;i<R;i++) o[i] = wx[i]*s;
}
__device__ __forceinline__ void wmid3_p(const float* a, const float* b, const float* c, float* o){
  float la = 2.f/(1.f - wdot<4>(a,a));
  float lb = 2.f/(1.f - wdot<4>(b,b));
  float lc = 2.f/(1.f - wdot<4>(c,c));
  float den = fmaxf(fabsf(la+lb+lc-3.f), EPSF);
  #pragma unroll
  for(int i=0;i<4;i++) o[i] = (la*a[i]+lb*b[i]+lc*c[i])/den;
  smul_p<4>(0.5f, o);
}
__device__ __forceinline__ void softmax8(float* s){
  float m = s[0];
  #pragma unroll
  for(int k=1;k<8;k++) m = fmaxf(m, s[k]);
  float sum = 0.f;
  #pragma unroll
  for(int k=0;k<8;k++){ s[k] = expf(s[k]-m); sum += s[k]; }
  float inv = 1.f/sum;
  #pragma unroll
  for(int k=0;k<8;k++) s[k] *= inv;
}

// ----------------------------- GEMM tile: C[64,128] += A[64,128] @ W[128cols]^T -----------------------------
__device__ __forceinline__ void gemm_tile(const float* __restrict__ A, const float* __restrict__ W,
                                          const float* __restrict__ bias, float* __restrict__ C, int HO){
  __shared__ float As[16][64];
  __shared__ float Bs[16][128];
  const int m0 = blockIdx.x * 64;
  const int n0 = blockIdx.y * 128;
  const int t = threadIdx.x;
  const int tx = t & 15, ty = t >> 4;
  float acc[4][8];
  #pragma unroll
  for(int i=0;i<4;i++)
    #pragma unroll
    for(int j=0;j<8;j++) acc[i][j]=0.f;
  for(int kc=0; kc<128; kc+=16){
    {
      int m = t >> 2, q = t & 3;
      float4 v = *(const float4*)(A + (m0+m)*128 + kc + q*4);
      As[q*4+0][m]=v.x; As[q*4+1][m]=v.y; As[q*4+2][m]=v.z; As[q*4+3][m]=v.w;
    }
    #pragma unroll
    for(int r=0;r<2;r++){
      int idx = t + r*256;
      int n = idx >> 2, q = idx & 3;
      float4 v = *(const float4*)(W + (n0+n)*128 + kc + q*4);
      Bs[q*4+0][n]=v.x; Bs[q*4+1][n]=v.y; Bs[q*4+2][n]=v.z; Bs[q*4+3][n]=v.w;
    }
    __syncthreads();
    #pragma unroll
    for(int k=0;k<16;k++){
      float4 av = *(const float4*)&As[k][tx*4];
      float4 b0 = *(const float4*)&Bs[k][ty*8];
      float4 b1 = *(const float4*)&Bs[k][ty*8+4];
      float a[4]={av.x,av.y,av.z,av.w};
      float b[8]={b0.x,b0.y,b0.z,b0.w,b1.x,b1.y,b1.z,b1.w};
      #pragma unroll
      for(int i=0;i<4;i++)
        #pragma unroll
        for(int j=0;j<8;j++) acc[i][j] += a[i]*b[j];
    }
    __syncthreads();
  }
  #pragma unroll
  for(int i=0;i<4;i++){
    int m = m0 + tx*4 + i;
    #pragma unroll
    for(int j=0;j<8;j++){
      int n = n0 + ty*8 + j;
      C[m*HO + n] = acc[i][j] + bias[n];
    }
  }
}

struct GArgs {
  const float* x; const float* h3; const float* c3;
  const float* Wq; const float* bq; const float* Wc; const float* bc;
  const float* Uf; const float* bf; const float* Up; const float* bp;
};

__global__ void k_gemm1(GArgs ga){
  const float* A; const float* W; const float* B; float* C;
  switch(blockIdx.z){
    case 0: A=ga.x;   W=ga.Wq; B=ga.bq; C=g_Yq;   break;
    case 1: A=g_l1;   W=ga.Up; B=ga.bp; C=g_Yup1; break;
    case 2: A=g_l2;   W=ga.Up; B=ga.bp; C=g_Yup2; break;
    case 3: A=ga.h3;  W=ga.Up; B=ga.bp; C=g_Yup3; break;
    case 4: A=g_l1;   W=ga.Uf; B=ga.bf; C=g_Yuf1; break;
    case 5: A=g_l2;   W=ga.Uf; B=ga.bf; C=g_Yuf2; break;
    case 6: A=ga.h3;  W=ga.Uf; B=ga.bf; C=g_Yuf3; break;
    case 7: A=g_lc1;  W=ga.Wc; B=ga.bc; C=g_Ywc1; break;
    case 8: A=g_lc2;  W=ga.Wc; B=ga.bc; C=g_Ywc2; break;
    default:A=ga.c3;  W=ga.Wc; B=ga.bc; C=g_Ywc3; break;
  }
  gemm_tile(A, W, B, C, 128);
}

__global__ void k_gemm2(const float* __restrict__ W, const float* __restrict__ B){
  const float* A; float* C;
  switch(blockIdx.z){
    case 0: A=g_A1; C=g_Z1; break;
    case 1: A=g_A2; C=g_Z2; break;
    default:A=g_A3; C=g_Z3; break;
  }
  gemm_tile(A, W, B, C, 384);
}

// ----------------------------- prep: logmaps of h1,h2,c1,c2 -----------------------------
__global__ void k_prep(const float* __restrict__ h1, const float* __restrict__ c1,
                       const float* __restrict__ h2, const float* __restrict__ c2){
  int n = (blockIdx.x*blockDim.x + threadIdx.x) >> 5;
  if(n >= NN) return;
  int l = threadIdx.x & 31;
  int b = n*128 + l*4;
  float v[4];
  ld4(v, h1+b); logmap0_p<4>(v); st4(g_l1+b, v);
  ld4(v, h2+b); logmap0_s<4>(v); st4(g_l2+b, v);
  ld4(v, c1+b); logmap0_p<4>(v); st4(g_lc1+b, v);
  ld4(v, c2+b); logmap0_s<4>(v); st4(g_lc2+b, v);
}

// ----------------------------- per-node elementwise -----------------------------
__global__ void k_node(const float* __restrict__ h1, const float* __restrict__ h2,
                       const float* __restrict__ h3, const float* __restrict__ c1,
                       const float* __restrict__ c2, const float* __restrict__ c3,
                       const float* __restrict__ del_t, const float* __restrict__ dptr){
  int n = (blockIdx.x*blockDim.x + threadIdx.x) >> 5;
  if(n >= NN) return;
  int l = threadIdx.x & 31;
  int b = n*128 + l*4;

  // query projections
  float yq[4]; ld4(yq, g_Yq+b);
  float v[4];
  cp4(v, yq); expmap0_p<4>(v); st4(g_x1p+b, v);
  cp4(v, yq); expmap0_s<4>(v); st4(g_x1s+b, v);

  // gates s1,s2,s3
  float s1[4]; ld4(s1, g_Yup1+b); expmap0_p<4>(s1); sigm<4>(s1); logmap0_p<4>(s1);
  float s2[4]; ld4(s2, g_Yup2+b); expmap0_s<4>(s2); sigm<4>(s2); logmap0_s<4>(s2);
  float s3[4]; ld4(s3, g_Yup3+b); sigm<4>(s3);

  float h1v[4]; ld4(h1v, h1+b);
  float h2v[4]; ld4(h2v, h2+b);
  float h3v[4]; ld4(h3v, h3+b);
  float l1v[4]; ld4(l1v, g_l1+b);

  // Poincare h-branch
  float ht1p[4]; pwmul_p<4>(s1, h1v, ht1p);
  float tmp[4];
  cp4(tmp, h2v); logmap0_s<4>(tmp); expmap0_p<4>(tmp);
  float ht2p[4]; pwmul_p<4>(s2, tmp, ht2p);
  cp4(tmp, h3v); expmap0_p<4>(tmp);
  float ht3p[4]; pwmul_p<4>(s3, tmp, ht3p);
  float h1pv[4]; wmid3_p(ht1p, ht2p, ht3p, h1pv);
  #pragma unroll
  for(int i=0;i<4;i++) h1pv[i] *= 3.f;
  st4(g_h1p+b, h1pv);
  float lamHp = 2.f/(1.f - wdot<4>(h1pv,h1pv));
  if(l==0) g_lamHp[n] = lamHp;

  // Sphere h-branch
  cp4(tmp, l1v); expmap0_s<4>(tmp);
  float ht1s[4]; pwmul_p<4>(s1, tmp, ht1s);
  float ht2s[4]; pwmul_s<4>(s2, h2v, ht2s);
  cp4(tmp, h3v); expmap0_s<4>(tmp);
  float ht3s[4]; pwmul_s<4>(s3, tmp, ht3s);
  float h1sv[4]; wmid3_p(ht1s, ht2s, ht3s, h1sv);
  #pragma unroll
  for(int i=0;i<4;i++) h1sv[i] *= 3.f;
  st4(g_h1s+b, h1sv);
  float lamHs = 2.f/(1.f + wdot<4>(h1sv,h1sv));
  if(l==0) g_lamHs[n] = lamHs;

  // Euclid h-branch: logmap0_p(ht1p) + logmap0_s(ht2s) + s3*h3
  float e1[4]; cp4(e1, ht1p); logmap0_p<4>(e1);
  float e2[4]; cp4(e2, ht2s); logmap0_s<4>(e2);
  float h1ev[4];
  #pragma unroll
  for(int i=0;i<4;i++) h1ev[i] = e1[i] + e2[i] + s3[i]*h3v[i];
  st4(g_h1e+b, h1ev);

  float g = dptr[0] / (del_t[n] + 1.f);

  // Poincare cell
  float c1v[4]; ld4(c1v, c1+b);
  float cskp[4]; ld4(cskp, g_Ywc1+b);
  expmap0_p<4>(cskp); logmap0_p<4>(cskp); tanhv<4>(cskp); expmap0_p<4>(cskp);
  float nk[4];
  #pragma unroll
  for(int i=0;i<4;i++) nk[i] = -cskp[i];
  float t1[4]; madd_p<4>(nk, c1v, t1);
  float t2[4]; pwmulg_p<4>(cskp, g, t2);
  float cktp[4]; madd_p<4>(t1, t2, cktp);
  float fp[4]; ld4(fp, g_Yuf1+b); expmap0_p<4>(fp); logmap0_p<4>(fp); sigm<4>(fp);
  float P1[4]; pwmul_p<4>(fp, cktp, P1);
  st4(g_P1+b, P1);
  float lam1 = 2.f/(1.f - wdot<4>(P1,P1));
  if(l==0) g_lam1[n] = lam1;

  // Sphere cell
  float c2v[4]; ld4(c2v, c2+b);
  float csks[4]; ld4(csks, g_Ywc2+b);
  expmap0_s<4>(csks); logmap0_s<4>(csks); tanhv<4>(csks); expmap0_s<4>(csks);
  #pragma unroll
  for(int i=0;i<4;i++) nk[i] = -csks[i];
  madd_s<4>(nk, c2v, t1);
  pwmulg_s<4>(csks, g, t2);
  float ckts[4]; madd_s<4>(t1, t2, ckts);
  float fs[4]; ld4(fs, g_Yuf2+b); expmap0_s<4>(fs); logmap0_s<4>(fs); sigm<4>(fs);
  float P2[4]; pwmul_s<4>(fs, ckts, P2);
  st4(g_P2+b, P2);
  float lam2 = 2.f/(1.f + wdot<4>(P2,P2));
  if(l==0) g_lam2[n] = lam2;

  // Euclid cell
  float c3v[4]; ld4(c3v, c3+b);
  float cske[4]; ld4(cske, g_Ywc3+b); tanhv<4>(cske);
  float fe[4]; ld4(fe, g_Yuf3+b); sigm<4>(fe);
  float E3[4];
  #pragma unroll
  for(int i=0;i<4;i++) E3[i] = fe[i]*(c3v[i] - cske[i] + cske[i]*g);
  st4(g_E3+b, E3);
}

// ----------------------------- gather + attention + cell reductions -----------------------------
__global__ void k_attn(const int* __restrict__ nbr){
  int n = (blockIdx.x*blockDim.x + threadIdx.x) >> 5;
  if(n >= NN) return;
  int l = threadIdx.x & 31;
  int b = n*128 + l*4;
  const int* nb = nbr + n*8;
  float sc[8];

  // ---- Poincare attention -> g_A1 = logmap0_p(h_tildp)
  {
    float xq[4]; ld4(xq, g_x1p+b);
    float x2 = wdot<4>(xq,xq);
    #pragma unroll
    for(int k=0;k<8;k++){
      int j = nb[k];
      float hk[4]; ld4(hk, g_h1p + j*128 + l*4);
      float y2 = wdot<4>(hk,hk);
      float xys = 0.f;
      #pragma unroll
      for(int i=0;i<4;i++) xys += (-xq[i])*hk[i];
      float xy = wred(xys);
      float cx = 1.f + 2.f*xy + y2;
      float cy = 1.f - x2;
      float dn = safe_den(1.f + 2.f*xy + x2*y2);
      float o[4];
      #pragma unroll
      for(int i=0;i<4;i++) o[i] = (cx*(-xq[i]) + cy*hk[i])/dn;
      float nr = fminf(wnrm<4>(o), PMF);
      sc[k] = -2.f*atanh_c(nr);
    }
    softmax8(sc);
    float num[4] = {0,0,0,0};
    float ds = 0.f;
    #pragma unroll
    for(int k=0;k<8;k++){
      int j = nb[k];
      float hk[4]; ld4(hk, g_h1p + j*128 + l*4);
      float lam = g_lamHp[j];
      #pragma unroll
      for(int i=0;i<4;i++) num[i] += sc[k]*lam*hk[i];
      ds += sc[k]*(lam - 1.f);
    }
    float den = fmaxf(fabsf(ds), EPSF);
    #pragma unroll
    for(int i=0;i<4;i++) num[i] /= den;
    smul_p<4>(0.5f, num);
    logmap0_p<4>(num);
    st4(g_A1+b, num);
  }

  // ---- Sphere attention -> g_A2 = logmap0_s(h_tilds)
  {
    float xq[4]; ld4(xq, g_x1s+b);
    float x2 = wdot<4>(xq,xq);
    #pragma unroll
    for(int k=0;k<8;k++){
      int j = nb[k];
      float hk[4]; ld4(hk, g_h1s + j*128 + l*4);
      float y2 = wdot<4>(hk,hk);
      float xys = 0.f;
      #pragma unroll
      for(int i=0;i<4;i++) xys += (-xq[i])*hk[i];
      float xy = wred(xys);
      float cx = 1.f - 2.f*xy - y2;
      float cy = 1.f + x2;
      float dn = safe_den(1.f - 2.f*xy + x2*y2);
      float o[4];
      #pragma unroll
      for(int i=0;i<4;i++) o[i] = (cx*(-xq[i]) + cy*hk[i])/dn;
      sc[k] = -2.f*atanf(wnrm<4>(o));
    }
    softmax8(sc);
    float num[4] = {0,0,0,0};
    float ds = 0.f;
    #pragma unroll
    for(int k=0;k<8;k++){
      int j = nb[k];
      float hk[4]; ld4(hk, g_h1s + j*128 + l*4);
      float lam = g_lamHs[j];
      #pragma unroll
      for(int i=0;i<4;i++) num[i] += sc[k]*lam*hk[i];
      ds += sc[k]*(lam - 1.f);
    }
    float den = fmaxf(fabsf(ds), EPSF);
    #pragma unroll
    for(int i=0;i<4;i++) num[i] /= den;
    smul_s<4>(0.5f, num);
    logmap0_s<4>(num);
    st4(g_A2+b, num);
  }

  // ---- Euclid attention -> g_A3 = h_tilde
  {
    float xq[4]; ld4(xq, g_Yq+b);
    const float isq = 1.f/sqrtf(128.f);
    #pragma unroll
    for(int k=0;k<8;k++){
      int j = nb[k];
      float hk[4]; ld4(hk, g_h1e + j*128 + l*4);
      sc[k] = wdot<4>(hk, xq) * isq;
    }
    softmax8(sc);
    float num[4] = {0,0,0,0};
    #pragma unroll
    for(int k=0;k<8;k++){
      int j = nb[k];
      float hk[4]; ld4(hk, g_h1e + j*128 + l*4);
      #pragma unroll
      for(int i=0;i<4;i++) num[i] += sc[k]*hk[i];
    }
    st4(g_A3+b, num);
  }

  // ---- cell reductions
  {
    float num[4] = {0,0,0,0};
    float ds = 0.f;
    #pragma unroll
    for(int k=0;k<8;k++){
      int j = nb[k];
      float pv[4]; ld4(pv, g_P1 + j*128 + l*4);
      float lam = g_lam1[j];
      #pragma unroll
      for(int i=0;i<4;i++) num[i] += lam*pv[i];
      ds += lam - 1.f;
    }
    float den = fmaxf(fabsf(ds), EPSF);
    #pragma unroll
    for(int i=0;i<4;i++) num[i] /= den;
    smul_p<4>(0.5f, num);
    st4(g_c1o+b, num);
  }
  {
    float num[4] = {0,0,0,0};
    float ds = 0.f;
    #pragma unroll
    for(int k=0;k<8;k++){
      int j = nb[k];
      float pv[4]; ld4(pv, g_P2 + j*128 + l*4);
      float lam = g_lam2[j];
      #pragma unroll
      for(int i=0;i<4;i++) num[i] += lam*pv[i];
      ds += lam - 1.f;
    }
    float den = fmaxf(fabsf(ds), EPSF);
    #pragma unroll
    for(int i=0;i<4;i++) num[i] /= den;
    smul_s<4>(0.5f, num);
    st4(g_c2o+b, num);
  }
  {
    float acc[4] = {0,0,0,0};
    #pragma unroll
    for(int k=0;k<8;k++){
      int j = nb[k];
      float ev[4]; ld4(ev, g_E3 + j*128 + l*4);
      #pragma unroll
      for(int i=0;i<4;i++) acc[i] += ev[i];
    }
    st4(g_c3o+b, acc);
  }
}

// ----------------------------- final epilogue -----------------------------
__global__ void k_final(const float* __restrict__ iou1, const float* __restrict__ iou2,
                        const float* __restrict__ iou3, float* __restrict__ out){
  int n = (blockIdx.x*blockDim.x + threadIdx.x) >> 5;
  if(n >= NN) return;
  int l = threadIdx.x & 31;
  int b = n*128 + l*4;
  int b3 = n*384 + l*4;

  // ---- Poincare
  {
    float z[12], io[12];
    #pragma unroll
    for(int c=0;c<3;c++){ ld4(z+4*c, g_Z1 + b3 + 128*c); ld4(io+4*c, iou1 + b3 + 128*c); }
    expmap0_p<12>(z);
    float ni[12]; madd_p<12>(io, z, ni);
    float ip[4], op[4], up[4];
    cp4(ip, ni+0); logmap0_p<4>(ip); sigm<4>(ip);
    cp4(op, ni+4); logmap0_p<4>(op); sigm<4>(op);
    cp4(up, ni+8); logmap0_p<4>(up); tanhv<4>(up);
    float t[4]; pwmul_p<4>(ip, up, t);
    float cc[4]; ld4(cc, g_c1o+b);
    float nc[4]; madd_p<4>(t, cc, nc);
    float lt[4]; cp4(lt, nc); logmap0_p<4>(lt); tanhv<4>(lt);
    float nh[4]; pwmul_p<4>(op, lt, nh);
    st4(out + 0*NN*128 + b, nh);
    st4(out + 1*NN*128 + b, nc);
  }
  // ---- Sphere
  {
    float z[12], io[12];
    #pragma unroll
    for(int c=0;c<3;c++){ ld4(z+4*c, g_Z2 + b3 + 128*c); ld4(io+4*c, iou2 + b3 + 128*c); }
    expmap0_s<12>(z);
    float ni[12]; madd_s<12>(io, z, ni);
    float ip[4], op[4], up[4];
    cp4(ip, ni+0); logmap0_s<4>(ip); sigm<4>(ip);
    cp4(op, ni+4); logmap0_s<4>(op); sigm<4>(op);
    cp4(up, ni+8); logmap0_s<4>(up); tanhv<4>(up);
    float t[4]; pwmul_s<4>(ip, up, t);
    float cc[4]; ld4(cc, g_c2o+b);
    float nc[4]; madd_s<4>(t, cc, nc);
    float lt[4]; cp4(lt, nc); logmap0_s<4>(lt); tanhv<4>(lt);
    float nh[4]; pwmul_s<4>(op, lt, nh);
    st4(out + 2*NN*128 + b, nh);
    st4(out + 3*NN*128 + b, nc);
  }
  // ---- Euclid
  {
    float z[12], io[12];
    #pragma unroll
    for(int c=0;c<3;c++){ ld4(z+4*c, g_Z3 + b3 + 128*c); ld4(io+4*c, iou3 + b3 + 128*c); }
    float ip[4], op[4], up[4];
    #pragma unroll
    for(int i=0;i<4;i++){
      ip[i] = io[i]   + z[i];
      op[i] = io[4+i] + z[4+i];
      up[i] = io[8+i] + z[8+i];
    }
    sigm<4>(ip); sigm<4>(op); tanhv<4>(up);
    float cc[4]; ld4(cc, g_c3o+b);
    float nc[4], nh[4];
    #pragma unroll
    for(int i=0;i<4;i++){
      nc[i] = ip[i]*up[i] + cc[i];
      nh[i] = op[i]*tanhf(nc[i]);
    }
    st4(out + 4*NN*128 + b, nh);
    st4(out + 5*NN*128 + b, nc);
  }
}

// ----------------------------- launch -----------------------------
extern "C" void kernel_launch(void* const* d_in, const int* in_sizes, int n_in,
                              void* d_out, int out_size){
  const float* x     = (const float*)d_in[0];
  const float* h1    = (const float*)d_in[1];
  const float* c1    = (const float*)d_in[2];
  const float* h2    = (const float*)d_in[3];
  const float* c2    = (const float*)d_in[4];
  const float* h3    = (const float*)d_in[5];
  const float* c3    = (const float*)d_in[6];
  const float* del_t = (const float*)d_in[7];
  const float* iou1  = (const float*)d_in[8];
  const float* iou2  = (const float*)d_in[9];
  const float* iou3  = (const float*)d_in[10];
  const float* Wq_w  = (const float*)d_in[11];
  const float* Wq_b  = (const float*)d_in[12];
  const float* Wc_w  = (const float*)d_in[13];
  const float* Wc_b  = (const float*)d_in[14];
  const float* Uf_w  = (const float*)d_in[15];
  const float* Uf_b  = (const float*)d_in[16];
  const float* Up_w  = (const float*)d_in[17];
  const float* Up_b  = (const float*)d_in[18];
  const float* Uiou_w= (const float*)d_in[19];
  const float* Uiou_b= (const float*)d_in[20];
  const float* dptr  = (const float*)d_in[21];
  const int*   nbr   = (const int*)d_in[22];
  float* out = (float*)d_out;

  k_prep<<<NN/8, 256>>>(h1, c1, h2, c2);

  GArgs ga;
  ga.x = x; ga.h3 = h3; ga.c3 = c3;
  ga.Wq = Wq_w; ga.bq = Wq_b;
  ga.Wc = Wc_w; ga.bc = Wc_b;
  ga.Uf = Uf_w; ga.bf = Uf_b;
  ga.Up = Up_w; ga.bp = Up_b;
  k_gemm1<<<dim3(NN/64, 1, 10), 256>>>(ga);

  k_node<<<NN/8, 256>>>(h1, h2, h3, c1, c2, c3, del_t, dptr);
  k_attn<<<NN/8, 256>>>(nbr);
  k_gemm2<<<dim3(NN/64, 3, 3), 256>>>(Uiou_w, Uiou_b);
  k_final<<<NN/8, 256>>>(iou1, iou2, iou3, out);
}

// round 4
// speedup vs baseline: 1.3107x; 1.3107x over previous
#include <cuda_runtime.h>
#include <math.h>
#include <stdint.h>

#define NN 8192
#define HH 128
#define H3 384
#define EPSF 1e-6f
#define PMF 0.9999f
#define PAD 132
#define GSMEM ((64 + 128) * PAD * 4)

// ----------------------------- scratch -----------------------------
__device__ float g_l1[NN*HH], g_l2[NN*HH], g_lc1[NN*HH], g_lc2[NN*HH];
__device__ float g_Yq[NN*HH];
__device__ float g_Yup1[NN*HH], g_Yup2[NN*HH], g_Yup3[NN*HH];
__device__ float g_Yuf1[NN*HH], g_Yuf2[NN*HH], g_Yuf3[NN*HH];
__device__ float g_Ywc1[NN*HH], g_Ywc2[NN*HH], g_Ywc3[NN*HH];
__device__ float g_x1p[NN*HH], g_x1s[NN*HH];
__device__ float g_h1p[NN*HH], g_h1s[NN*HH], g_h1e[NN*HH];
__device__ float g_P1[NN*HH], g_P2[NN*HH], g_E3[NN*HH];
__device__ float g_A1[NN*HH], g_A2[NN*HH], g_A3[NN*HH];
__device__ float g_c1o[NN*HH], g_c2o[NN*HH], g_c3o[NN*HH];
__device__ float g_Z1[NN*H3], g_Z2[NN*H3], g_Z3[NN*H3];

// ----------------------------- helpers -----------------------------
__device__ __forceinline__ float wred(float s){
  #pragma unroll
  for(int o=16;o;o>>=1) s += __shfl_xor_sync(0xffffffffu, s, o);
  return s;
}
template<int R> __device__ __forceinline__ float wdot(const float* a, const float* b){
  float s=0.f;
  #pragma unroll
  for(int i=0;i<R;i++) s += a[i]*b[i];
  return wred(s);
}
template<int R> __device__ __forceinline__ float wnrm(const float* a){
  return sqrtf(wdot<R>(a,a) + 1e-15f);
}
__device__ __forceinline__ float atanh_c(float u){
  u = fminf(fmaxf(u, -1.0f+1e-5f), 1.0f-1e-5f);
  return atanhf(u);
}
__device__ __forceinline__ float tan_c(float u){
  u = fminf(fmaxf(u, -1.47079f), 1.47079f);
  return tanf(u);
}
__device__ __forceinline__ float safe_den(float d){
  return d >= 0.f ? fmaxf(d, EPSF) : fminf(d, -EPSF);
}
__device__ __forceinline__ void ld4(float* v, const float* p){
  float4 t = *(const float4*)p; v[0]=t.x; v[1]=t.y; v[2]=t.z; v[3]=t.w;
}
__device__ __forceinline__ void st4(float* p, const float* v){
  *(float4*)p = make_float4(v[0],v[1],v[2],v[3]);
}
__device__ __forceinline__ void cp4(float* d, const float* s){
  #pragma unroll
  for(int i=0;i<4;i++) d[i]=s[i];
}
template<int R> __device__ __forceinline__ void sigm(float* v){
  #pragma unroll
  for(int i=0;i<R;i++) v[i] = 1.f/(1.f+expf(-v[i]));
}
template<int R> __device__ __forceinline__ void tanhv(float* v){
  #pragma unroll
  for(int i=0;i<R;i++) v[i] = tanhf(v[i]);
}
template<int R> __device__ __forceinline__ void proj_p(float* v){
  float n = wnrm<R>(v);
  if(n > PMF){
    float s = PMF/n;
    #pragma unroll
    for(int i=0;i<R;i++) v[i]*=s;
  }
}
template<int R> __device__ __forceinline__ void expmap0_p(float* v){
  float n = wnrm<R>(v); float s = tanhf(n)/n;
  #pragma unroll
  for(int i=0;i<R;i++) v[i]*=s;
  proj_p<R>(v);
}
template<int R> __device__ __forceinline__ void logmap0_p(float* v){
  float n = wnrm<R>(v); float s = atanh_c(n)/n;
  #pragma unroll
  for(int i=0;i<R;i++) v[i]*=s;
}
template<int R> __device__ __forceinline__ void expmap0_s(float* v){
  float n = wnrm<R>(v); float s = tan_c(n)/n;
  #pragma unroll
  for(int i=0;i<R;i++) v[i]*=s;
}
template<int R> __device__ __forceinline__ void logmap0_s(float* v){
  float n = wnrm<R>(v); float s = atanf(n)/n;
  #pragma unroll
  for(int i=0;i<R;i++) v[i]*=s;
}
template<int R> __device__ __forceinline__ void smul_p(float r, float* v){
  float n = wnrm<R>(v); float s = tanhf(r*atanh_c(n))/n;
  #pragma unroll
  for(int i=0;i<R;i++) v[i]*=s;
  proj_p<R>(v);
}
template<int R> __device__ __forceinline__ void smul_s(float r, float* v){
  float n = wnrm<R>(v); float s = tan_c(r*atanf(n))/n;
  #pragma unroll
  for(int i=0;i<R;i++) v[i]*=s;
}
template<int R> __device__ __forceinline__ void madd_p(const float* x, const float* y, float* o){
  float x2 = wdot<R>(x,x), y2 = wdot<R>(y,y), xy = wdot<R>(x,y);
  float cx = 1.f + 2.f*xy + y2;
  float cy = 1.f - x2;
  float dn = safe_den(1.f + 2.f*xy + x2*y2);
  #pragma unroll
  for(int i=0;i<R;i++) o[i] = (cx*x[i] + cy*y[i])/dn;
  proj_p<R>(o);
}
template<int R> __device__ __forceinline__ void madd_s(const float* x, const float* y, float* o){
  float x2 = wdot<R>(x,x), y2 = wdot<R>(y,y), xy = wdot<R>(x,y);
  float cx = 1.f - 2.f*xy - y2;
  float cy = 1.f + x2;
  float dn = safe_den(1.f - 2.f*xy + x2*y2);
  #pragma unroll
  for(int i=0;i<R;i++) o[i] = (cx*x[i] + cy*y[i])/dn;
}
template<int R> __device__ __forceinline__ void pwmul_p(const float* w, const float* x, float* o){
  float wx[R];
  #pragma unroll
  for(int i=0;i<R;i++) wx[i] = w[i]*x[i];
  float nx = wnrm<R>(x), nwx = wnrm<R>(wx);
  float s = tanhf(nwx/nx*atanh_c(nx))/nwx;
  #pragma unroll
  for(int i=0;i<R;i++) o[i] = wx[i]*s;
  proj_p<R>(o);
}
template<int R> __device__ __forceinline__ void pwmul_s(const float* w, const float* x, float* o){
  float wx[R];
  #pragma unroll
  for(int i=0;i<R;i++) wx[i] = w[i]*x[i];
  float nx = wnrm<R>(x), nwx = wnrm<R>(wx);
  float s = tan_c(nwx/nx*atanf(nx))/nwx;
  #pragma unroll
  for(int i=0;i<R;i++) o[i] = wx[i]*s;
}
template<int R> __device__ __forceinline__ void pwmulg_p(const float* w, float g, float* o){
  float wx[R];
  #pragma unroll
  for(int i=0;i<R;i++) wx[i] = w[i]*g;
  float nx = sqrtf(g*g + 1e-15f), nwx = wnrm<R>(wx);
  float s = tanhf(nwx/nx*atanh_c(nx))/nwx;
  #pragma unroll
  for(int i=0;i<R;i++) o[i] = wx[i]*s;
  proj_p<R>(o);
}
template<int R> __device__ __forceinline__ void pwmulg_s(const float* w, float g, float* o){
  float wx[R];
  #pragma unroll
  for(int i=0;i<R;i++) wx[i] = w[i]*g;
  float nx = sqrtf(g*g + 1e-15f), nwx = wnrm<R>(wx);
  float s = tan_c(nwx/nx*atanf(nx))/nwx;
  #pragma unroll
  for(int i=0;i<R;i++) o[i] = wx[i]*s;
}
__device__ __forceinline__ void wmid3_p(const float* a, const float* b, const float* c, float* o){
  float la = 2.f/(1.f - wdot<4>(a,a));
  float lb = 2.f/(1.f - wdot<4>(b,b));
  float lc = 2.f/(1.f - wdot<4>(c,c));
  float den = fmaxf(fabsf(la+lb+lc-3.f), EPSF);
  #pragma unroll
  for(int i=0;i<4;i++) o[i] = (la*a[i]+lb*b[i]+lc*c[i])/den;
  smul_p<4>(0.5f, o);
}
__device__ __forceinline__ void softmax8(float* s){
  float m = s[0];
  #pragma unroll
  for(int k=1;k<8;k++) m = fmaxf(m, s[k]);
  float sum = 0.f;
  #pragma unroll
  for(int k=0;k<8;k++){ s[k] = expf(s[k]-m); sum += s[k]; }
  float inv = 1.f/sum;
  #pragma unroll
  for(int k=0;k<8;k++) s[k] *= inv;
}

// ----------------------------- tf32 mma GEMM -----------------------------
__device__ __forceinline__ uint32_t cvt_tf32(float x){
  uint32_t u; asm("cvt.rna.tf32.f32 %0, %1;" : "=r"(u) : "f"(x)); return u;
}
__device__ __forceinline__ void hilo(float x, uint32_t& h, uint32_t& l){
  h = cvt_tf32(x);
  l = cvt_tf32(x - __uint_as_float(h));
}
__device__ __forceinline__ void mma8(float* d, const uint32_t* a, const uint32_t* bb){
  asm volatile("mma.sync.aligned.m16n8k8.row.col.f32.tf32.tf32.f32 "
    "{%0,%1,%2,%3},{%4,%5,%6,%7},{%8,%9},{%0,%1,%2,%3};"
    : "+f"(d[0]),"+f"(d[1]),"+f"(d[2]),"+f"(d[3])
    : "r"(a[0]),"r"(a[1]),"r"(a[2]),"r"(a[3]),"r"(bb[0]),"r"(bb[1]));
}

// C[m0:m0+64, n0:n0+128] = A[.,128] @ W[n,128]^T + bias, 256 threads
__device__ __forceinline__ void gemm_mma(const float* __restrict__ A, const float* __restrict__ W,
                                         const float* __restrict__ bias, float* __restrict__ C, int HO){
  extern __shared__ float sh[];
  float* As = sh;            // [64][PAD]
  float* Ws = sh + 64*PAD;   // [128][PAD]
  const int m0 = blockIdx.x*64;
  const int n0 = blockIdx.y*128;
  const int t = threadIdx.x;
  const int lane = t & 31, w = t >> 5;
  const int wm = w >> 2, wn = w & 3;     // warps 2x4
  const int gid = lane >> 2, tig = lane & 3;

  #pragma unroll
  for(int i=0;i<8;i++){
    int f = t + i*256; int r = f>>5, c4 = f&31;
    float4 v = *(const float4*)(A + (m0+r)*128 + c4*4);
    *(float4*)(As + r*PAD + c4*4) = v;
  }
  #pragma unroll
  for(int i=0;i<16;i++){
    int f = t + i*256; int r = f>>5, c4 = f&31;
    float4 v = *(const float4*)(W + (n0+r)*128 + c4*4);
    *(float4*)(Ws + r*PAD + c4*4) = v;
  }
  __syncthreads();

  float acc[2][4][4];
  #pragma unroll
  for(int mt=0;mt<2;mt++)
    #pragma unroll
    for(int nt=0;nt<4;nt++)
      #pragma unroll
      for(int i=0;i<4;i++) acc[mt][nt][i]=0.f;

  for(int kk=0;kk<128;kk+=8){
    uint32_t ah[2][4], al[2][4];
    #pragma unroll
    for(int mt=0;mt<2;mt++){
      int r = wm*32 + mt*16 + gid;
      float x0 = As[r*PAD       + kk + tig];
      float x1 = As[(r+8)*PAD   + kk + tig];
      float x2 = As[r*PAD       + kk + tig + 4];
      float x3 = As[(r+8)*PAD   + kk + tig + 4];
      hilo(x0, ah[mt][0], al[mt][0]);
      hilo(x1, ah[mt][1], al[mt][1]);
      hilo(x2, ah[mt][2], al[mt][2]);
      hilo(x3, ah[mt][3], al[mt][3]);
    }
    uint32_t bh[4][2], bl[4][2];
    #pragma unroll
    for(int nt=0;nt<4;nt++){
      int nrow = wn*32 + nt*8 + gid;
      float y0 = Ws[nrow*PAD + kk + tig];
      float y1 = Ws[nrow*PAD + kk + tig + 4];
      hilo(y0, bh[nt][0], bl[nt][0]);
      hilo(y1, bh[nt][1], bl[nt][1]);
    }
    #pragma unroll
    for(int mt=0;mt<2;mt++)
      #pragma unroll
      for(int nt=0;nt<4;nt++){
        mma8(acc[mt][nt], al[mt], bh[nt]);
        mma8(acc[mt][nt], ah[mt], bl[nt]);
        mma8(acc[mt][nt], ah[mt], bh[nt]);
      }
  }

  #pragma unroll
  for(int mt=0;mt<2;mt++){
    int r = m0 + wm*32 + mt*16 + gid;
    #pragma unroll
    for(int nt=0;nt<4;nt++){
      int c = n0 + wn*32 + nt*8 + tig*2;
      float b0 = bias[c], b1 = bias[c+1];
      *(float2*)(C + r*HO + c)     = make_float2(acc[mt][nt][0]+b0, acc[mt][nt][1]+b1);
      *(float2*)(C + (r+8)*HO + c) = make_float2(acc[mt][nt][2]+b0, acc[mt][nt][3]+b1);
    }
  }
}

struct GArgs {
  const float* x; const float* h3; const float* c3;
  const float* Wq; const float* bq; const float* Wc; const float* bc;
  const float* Uf; const float* bf; const float* Up; const float* bp;
};

__global__ void __launch_bounds__(256) k_gemm1(GArgs ga){
  const float* A; const float* W; const float* B; float* C;
  switch(blockIdx.z){
    case 0: A=ga.x;   W=ga.Wq; B=ga.bq; C=g_Yq;   break;
    case 1: A=g_l1;   W=ga.Up; B=ga.bp; C=g_Yup1; break;
    case 2: A=g_l2;   W=ga.Up; B=ga.bp; C=g_Yup2; break;
    case 3: A=ga.h3;  W=ga.Up; B=ga.bp; C=g_Yup3; break;
    case 4: A=g_l1;   W=ga.Uf; B=ga.bf; C=g_Yuf1; break;
    case 5: A=g_l2;   W=ga.Uf; B=ga.bf; C=g_Yuf2; break;
    case 6: A=ga.h3;  W=ga.Uf; B=ga.bf; C=g_Yuf3; break;
    case 7: A=g_lc1;  W=ga.Wc; B=ga.bc; C=g_Ywc1; break;
    case 8: A=g_lc2;  W=ga.Wc; B=ga.bc; C=g_Ywc2; break;
    default:A=ga.c3;  W=ga.Wc; B=ga.bc; C=g_Ywc3; break;
  }
  gemm_mma(A, W, B, C, 128);
}

__global__ void __launch_bounds__(256) k_gemm2(const float* __restrict__ W, const float* __restrict__ B){
  const float* A; float* C;
  switch(blockIdx.z){
    case 0: A=g_A1; C=g_Z1; break;
    case 1: A=g_A2; C=g_Z2; break;
    default:A=g_A3; C=g_Z3; break;
  }
  gemm_mma(A, W, B, C, 384);
}

// ----------------------------- prep -----------------------------
__global__ void k_prep(const float* __restrict__ h1, const float* __restrict__ c1,
                       const float* __restrict__ h2, const float* __restrict__ c2){
  int n = (blockIdx.x*blockDim.x + threadIdx.x) >> 5;
  if(n >= NN) return;
  int l = threadIdx.x & 31;
  int b = n*128 + l*4;
  float v[4];
  ld4(v, h1+b); logmap0_p<4>(v); st4(g_l1+b, v);
  ld4(v, h2+b); logmap0_s<4>(v); st4(g_l2+b, v);
  ld4(v, c1+b); logmap0_p<4>(v); st4(g_lc1+b, v);
  ld4(v, c2+b); logmap0_s<4>(v); st4(g_lc2+b, v);
}

// ----------------------------- per-node elementwise -----------------------------
__global__ void k_node(const float* __restrict__ h1, const float* __restrict__ h2,
                       const float* __restrict__ h3, const float* __restrict__ c1,
                       const float* __restrict__ c2, const float* __restrict__ c3,
                       const float* __restrict__ del_t, const float* __restrict__ dptr){
  int n = (blockIdx.x*blockDim.x + threadIdx.x) >> 5;
  if(n >= NN) return;
  int l = threadIdx.x & 31;
  int b = n*128 + l*4;

  float yq[4]; ld4(yq, g_Yq+b);
  float v[4];
  cp4(v, yq); expmap0_p<4>(v); st4(g_x1p+b, v);
  cp4(v, yq); expmap0_s<4>(v); st4(g_x1s+b, v);

  float s1[4]; ld4(s1, g_Yup1+b); expmap0_p<4>(s1); sigm<4>(s1); logmap0_p<4>(s1);
  float s2[4]; ld4(s2, g_Yup2+b); expmap0_s<4>(s2); sigm<4>(s2); logmap0_s<4>(s2);
  float s3[4]; ld4(s3, g_Yup3+b); sigm<4>(s3);

  float h1v[4]; ld4(h1v, h1+b);
  float h2v[4]; ld4(h2v, h2+b);
  float h3v[4]; ld4(h3v, h3+b);
  float l1v[4]; ld4(l1v, g_l1+b);

  // Poincare h-branch
  float ht1p[4]; pwmul_p<4>(s1, h1v, ht1p);
  float tmp[4];
  cp4(tmp, h2v); logmap0_s<4>(tmp); expmap0_p<4>(tmp);
  float ht2p[4]; pwmul_p<4>(s2, tmp, ht2p);
  cp4(tmp, h3v); expmap0_p<4>(tmp);
  float ht3p[4]; pwmul_p<4>(s3, tmp, ht3p);
  float h1pv[4]; wmid3_p(ht1p, ht2p, ht3p, h1pv);
  #pragma unroll
  for(int i=0;i<4;i++) h1pv[i] *= 3.f;
  st4(g_h1p+b, h1pv);

  // Sphere h-branch
  cp4(tmp, l1v); expmap0_s<4>(tmp);
  float ht1s[4]; pwmul_p<4>(s1, tmp, ht1s);
  float ht2s[4]; pwmul_s<4>(s2, h2v, ht2s);
  cp4(tmp, h3v); expmap0_s<4>(tmp);
  float ht3s[4]; pwmul_s<4>(s3, tmp, ht3s);
  float h1sv[4]; wmid3_p(ht1s, ht2s, ht3s, h1sv);
  #pragma unroll
  for(int i=0;i<4;i++) h1sv[i] *= 3.f;
  st4(g_h1s+b, h1sv);

  // Euclid h-branch
  float e1[4]; cp4(e1, ht1p); logmap0_p<4>(e1);
  float e2[4]; cp4(e2, ht2s); logmap0_s<4>(e2);
  float h1ev[4];
  #pragma unroll
  for(int i=0;i<4;i++) h1ev[i] = e1[i] + e2[i] + s3[i]*h3v[i];
  st4(g_h1e+b, h1ev);

  float g = dptr[0] / (del_t[n] + 1.f);

  // Poincare cell
  float c1v[4]; ld4(c1v, c1+b);
  float cskp[4]; ld4(cskp, g_Ywc1+b);
  expmap0_p<4>(cskp); logmap0_p<4>(cskp); tanhv<4>(cskp); expmap0_p<4>(cskp);
  float nk[4];
  #pragma unroll
  for(int i=0;i<4;i++) nk[i] = -cskp[i];
  float t1[4]; madd_p<4>(nk, c1v, t1);
  float t2[4]; pwmulg_p<4>(cskp, g, t2);
  float cktp[4]; madd_p<4>(t1, t2, cktp);
  float fp[4]; ld4(fp, g_Yuf1+b); expmap0_p<4>(fp); logmap0_p<4>(fp); sigm<4>(fp);
  float P1[4]; pwmul_p<4>(fp, cktp, P1);
  st4(g_P1+b, P1);

  // Sphere cell
  float c2v[4]; ld4(c2v, c2+b);
  float csks[4]; ld4(csks, g_Ywc2+b);
  expmap0_s<4>(csks); logmap0_s<4>(csks); tanhv<4>(csks); expmap0_s<4>(csks);
  #pragma unroll
  for(int i=0;i<4;i++) nk[i] = -csks[i];
  madd_s<4>(nk, c2v, t1);
  pwmulg_s<4>(csks, g, t2);
  float ckts[4]; madd_s<4>(t1, t2, ckts);
  float fs[4]; ld4(fs, g_Yuf2+b); expmap0_s<4>(fs); logmap0_s<4>(fs); sigm<4>(fs);
  float P2[4]; pwmul_s<4>(fs, ckts, P2);
  st4(g_P2+b, P2);

  // Euclid cell
  float c3v[4]; ld4(c3v, c3+b);
  float cske[4]; ld4(cske, g_Ywc3+b); tanhv<4>(cske);
  float fe[4]; ld4(fe, g_Yuf3+b); sigm<4>(fe);
  float E3[4];
  #pragma unroll
  for(int i=0;i<4;i++) E3[i] = fe[i]*(c3v[i] - cske[i] + cske[i]*g);
  st4(g_E3+b, E3);
}

// ----------------------------- gather + attention + cell reductions -----------------------------
__global__ void k_attn(const int* __restrict__ nbr){
  int n = (blockIdx.x*blockDim.x + threadIdx.x) >> 5;
  if(n >= NN) return;
  int l = threadIdx.x & 31;
  int b = n*128 + l*4;
  const int* nb = nbr + n*8;
  int nj[8];
  #pragma unroll
  for(int k=0;k<8;k++) nj[k] = nb[k]*128 + l*4;

  int sec = blockIdx.y;
  if(sec == 0){
    // Poincare attention -> g_A1 = logmap0_p(h_tildp)
    float xq[4]; ld4(xq, g_x1p+b);
    float x2 = wdot<4>(xq,xq);
    float hk[8][4], y2[8], sc[8];
    #pragma unroll
    for(int k=0;k<8;k++){
      ld4(hk[k], g_h1p + nj[k]);
      float sy=0.f, sxy=0.f;
      #pragma unroll
      for(int i=0;i<4;i++){ sy += hk[k][i]*hk[k][i]; sxy -= xq[i]*hk[k][i]; }
      y2[k] = wred(sy);
      float xy = wred(sxy);
      float cx = 1.f + 2.f*xy + y2[k];
      float cy = 1.f - x2;
      float dn = safe_den(1.f + 2.f*xy + x2*y2[k]);
      float o[4];
      #pragma unroll
      for(int i=0;i<4;i++) o[i] = (cx*(-xq[i]) + cy*hk[k][i])/dn;
      sc[k] = -2.f*atanh_c(fminf(wnrm<4>(o), PMF));
    }
    softmax8(sc);
    float num[4] = {0,0,0,0};
    float ds = 0.f;
    #pragma unroll
    for(int k=0;k<8;k++){
      float lam = 2.f/(1.f - y2[k]);
      float wk = sc[k]*lam;
      #pragma unroll
      for(int i=0;i<4;i++) num[i] += wk*hk[k][i];
      ds += sc[k]*(lam - 1.f);
    }
    float den = fmaxf(fabsf(ds), EPSF);
    #pragma unroll
    for(int i=0;i<4;i++) num[i] /= den;
    smul_p<4>(0.5f, num);
    logmap0_p<4>(num);
    st4(g_A1+b, num);
  } else if(sec == 1){
    // Sphere attention -> g_A2 = logmap0_s(h_tilds)
    float xq[4]; ld4(xq, g_x1s+b);
    float x2 = wdot<4>(xq,xq);
    float hk[8][4], y2[8], sc[8];
    #pragma unroll
    for(int k=0;k<8;k++){
      ld4(hk[k], g_h1s + nj[k]);
      float sy=0.f, sxy=0.f;
      #pragma unroll
      for(int i=0;i<4;i++){ sy += hk[k][i]*hk[k][i]; sxy -= xq[i]*hk[k][i]; }
      y2[k] = wred(sy);
      float xy = wred(sxy);
      float cx = 1.f - 2.f*xy - y2[k];
      float cy = 1.f + x2;
      float dn = safe_den(1.f - 2.f*xy + x2*y2[k]);
      float o[4];
      #pragma unroll
      for(int i=0;i<4;i++) o[i] = (cx*(-xq[i]) + cy*hk[k][i])/dn;
      sc[k] = -2.f*atanf(wnrm<4>(o));
    }
    softmax8(sc);
    float num[4] = {0,0,0,0};
    float ds = 0.f;
    #pragma unroll
    for(int k=0;k<8;k++){
      float lam = 2.f/(1.f + y2[k]);
      float wk = sc[k]*lam;
      #pragma unroll
      for(int i=0;i<4;i++) num[i] += wk*hk[k][i];
      ds += sc[k]*(lam - 1.f);
    }
    float den = fmaxf(fabsf(ds), EPSF);
    #pragma unroll
    for(int i=0;i<4;i++) num[i] /= den;
    smul_s<4>(0.5f, num);
    logmap0_s<4>(num);
    st4(g_A2+b, num);
  } else if(sec == 2){
    // Euclid attention -> g_A3
    float xq[4]; ld4(xq, g_Yq+b);
    const float isq = 0.08838834764831845f; // 1/sqrt(128)
    float hk[8][4], sc[8];
    #pragma unroll
    for(int k=0;k<8;k++){
      ld4(hk[k], g_h1e + nj[k]);
      sc[k] = wdot<4>(hk[k], xq) * isq;
    }
    softmax8(sc);
    float num[4] = {0,0,0,0};
    #pragma unroll
    for(int k=0;k<8;k++){
      #pragma unroll
      for(int i=0;i<4;i++) num[i] += sc[k]*hk[k][i];
    }
    st4(g_A3+b, num);
  } else {
    // cell reductions
    {
      float num[4] = {0,0,0,0};
      float ds = 0.f;
      #pragma unroll
      for(int k=0;k<8;k++){
        float pv[4]; ld4(pv, g_P1 + nj[k]);
        float lam = 2.f/(1.f - wdot<4>(pv,pv));
        #pragma unroll
        for(int i=0;i<4;i++) num[i] += lam*pv[i];
        ds += lam - 1.f;
      }
      float den = fmaxf(fabsf(ds), EPSF);
      #pragma unroll
      for(int i=0;i<4;i++) num[i] /= den;
      smul_p<4>(0.5f, num);
      st4(g_c1o+b, num);
    }
    {
      float num[4] = {0,0,0,0};
      float ds = 0.f;
      #pragma unroll
      for(int k=0;k<8;k++){
        float pv[4]; ld4(pv, g_P2 + nj[k]);
        float lam = 2.f/(1.f + wdot<4>(pv,pv));
        #pragma unroll
        for(int i=0;i<4;i++) num[i] += lam*pv[i];
        ds += lam - 1.f;
      }
      float den = fmaxf(fabsf(ds), EPSF);
      #pragma unroll
      for(int i=0;i<4;i++) num[i] /= den;
      smul_s<4>(0.5f, num);
      st4(g_c2o+b, num);
    }
    {
      float acc[4] = {0,0,0,0};
      #pragma unroll
      for(int k=0;k<8;k++){
        float ev[4]; ld4(ev, g_E3 + nj[k]);
        #pragma unroll
        for(int i=0;i<4;i++) acc[i] += ev[i];
      }
      st4(g_c3o+b, acc);
    }
  }
}

// ----------------------------- final epilogue -----------------------------
__global__ void k_final(const float* __restrict__ iou1, const float* __restrict__ iou2,
                        const float* __restrict__ iou3, float* __restrict__ out){
  int n = (blockIdx.x*blockDim.x + threadIdx.x) >> 5;
  if(n >= NN) return;
  int l = threadIdx.x & 31;
  int b = n*128 + l*4;
  int b3 = n*384 + l*4;

  // Poincare
  {
    float z[12], io[12];
    #pragma unroll
    for(int c=0;c<3;c++){ ld4(z+4*c, g_Z1 + b3 + 128*c); ld4(io+4*c, iou1 + b3 + 128*c); }
    expmap0_p<12>(z);
    float ni[12]; madd_p<12>(io, z, ni);
    float ip[4], op[4], up[4];
    cp4(ip, ni+0); logmap0_p<4>(ip); sigm<4>(ip);
    cp4(op, ni+4); logmap0_p<4>(op); sigm<4>(op);
    cp4(up, ni+8); logmap0_p<4>(up); tanhv<4>(up);
    float t[4]; pwmul_p<4>(ip, up, t);
    float cc[4]; ld4(cc, g_c1o+b);
    float nc[4]; madd_p<4>(t, cc, nc);
    float lt[4]; cp4(lt, nc); logmap0_p<4>(lt); tanhv<4>(lt);
    float nh[4]; pwmul_p<4>(op, lt, nh);
    st4(out + 0*NN*128 + b, nh);
    st4(out + 1*NN*128 + b, nc);
  }
  // Sphere
  {
    float z[12], io[12];
    #pragma unroll
    for(int c=0;c<3;c++){ ld4(z+4*c, g_Z2 + b3 + 128*c); ld4(io+4*c, iou2 + b3 + 128*c); }
    expmap0_s<12>(z);
    float ni[12]; madd_s<12>(io, z, ni);
    float ip[4], op[4], up[4];
    cp4(ip, ni+0); logmap0_s<4>(ip); sigm<4>(ip);
    cp4(op, ni+4); logmap0_s<4>(op); sigm<4>(op);
    cp4(up, ni+8); logmap0_s<4>(up); tanhv<4>(up);
    float t[4]; pwmul_s<4>(ip, up, t);
    float cc[4]; ld4(cc, g_c2o+b);
    float nc[4]; madd_s<4>(t, cc, nc);
    float lt[4]; cp4(lt, nc); logmap0_s<4>(lt); tanhv<4>(lt);
    float nh[4]; pwmul_s<4>(op, lt, nh);
    st4(out + 2*NN*128 + b, nh);
    st4(out + 3*NN*128 + b, nc);
  }
  // Euclid
  {
    float z[12], io[12];
    #pragma unroll
    for(int c=0;c<3;c++){ ld4(z+4*c, g_Z3 + b3 + 128*c); ld4(io+4*c, iou3 + b3 + 128*c); }
    float ip[4], op[4], up[4];
    #pragma unroll
    for(int i=0;i<4;i++){
      ip[i] = io[i]   + z[i];
      op[i] = io[4+i] + z[4+i];
      up[i] = io[8+i] + z[8+i];
    }
    sigm<4>(ip); sigm<4>(op); tanhv<4>(up);
    float cc[4]; ld4(cc, g_c3o+b);
    float nc[4], nh[4];
    #pragma unroll
    for(int i=0;i<4;i++){
      nc[i] = ip[i]*up[i] + cc[i];
      nh[i] = op[i]*tanhf(nc[i]);
    }
    st4(out + 4*NN*128 + b, nh);
    st4(out + 5*NN*128 + b, nc);
  }
}

// ----------------------------- launch -----------------------------
extern "C" void kernel_launch(void* const* d_in, const int* in_sizes, int n_in,
                              void* d_out, int out_size){
  const float* x     = (const float*)d_in[0];
  const float* h1    = (const float*)d_in[1];
  const float* c1    = (const float*)d_in[2];
  const float* h2    = (const float*)d_in[3];
  const float* c2    = (const float*)d_in[4];
  const float* h3    = (const float*)d_in[5];
  const float* c3    = (const float*)d_in[6];
  const float* del_t = (const float*)d_in[7];
  const float* iou1  = (const float*)d_in[8];
  const float* iou2  = (const float*)d_in[9];
  const float* iou3  = (const float*)d_in[10];
  const float* Wq_w  = (const float*)d_in[11];
  const float* Wq_b  = (const float*)d_in[12];
  const float* Wc_w  = (const float*)d_in[13];
  const float* Wc_b  = (const float*)d_in[14];
  const float* Uf_w  = (const float*)d_in[15];
  const float* Uf_b  = (const float*)d_in[16];
  const float* Up_w  = (const float*)d_in[17];
  const float* Up_b  = (const float*)d_in[18];
  const float* Uiou_w= (const float*)d_in[19];
  const float* Uiou_b= (const float*)d_in[20];
  const float* dptr  = (const float*)d_in[21];
  const int*   nbr   = (const int*)d_in[22];
  float* out = (float*)d_out;

  cudaFuncSetAttribute(k_gemm1, cudaFuncAttributeMaxDynamicSharedMemorySize, GSMEM);
  cudaFuncSetAttribute(k_gemm2, cudaFuncAttributeMaxDynamicSharedMemorySize, GSMEM);

  k_prep<<<NN/8, 256>>>(h1, c1, h2, c2);

  GArgs ga;
  ga.x = x; ga.h3 = h3; ga.c3 = c3;
  ga.Wq = Wq_w; ga.bq = Wq_b;
  ga.Wc = Wc_w; ga.bc = Wc_b;
  ga.Uf = Uf_w; ga.bf = Uf_b;
  ga.Up = Up_w; ga.bp = Up_b;
  k_gemm1<<<dim3(NN/64, 1, 10), 256, GSMEM>>>(ga);

  k_node<<<NN/8, 256>>>(h1, h2, h3, c1, c2, c3, del_t, dptr);
  k_attn<<<dim3(NN/8, 4), 256>>>(nbr);
  k_gemm2<<<dim3(NN/64, 3, 3), 256, GSMEM>>>(Uiou_w, Uiou_b);
  k_final<<<NN/8, 256>>>(iou1, iou2, iou3, out);
}

// round 5
// speedup vs baseline: 1.6444x; 1.2546x over previous
#include <cuda_runtime.h>
#include <cuda_bf16.h>
#include <math.h>
#include <stdint.h>

#define NN 8192
#define HH 128
#define H3 384
#define EPSF 1e-6f
#define PMF 0.9999f
#define PADU 68
#define GSMEM (384 * PADU * 4)

// ----------------------------- scratch -----------------------------
__device__ float g_l1[NN*HH], g_l2[NN*HH], g_lc1[NN*HH], g_lc2[NN*HH];
__device__ float g_Yq[NN*HH];
__device__ float g_Yup1[NN*HH], g_Yup2[NN*HH], g_Yup3[NN*HH];
__device__ float g_Yuf1[NN*HH], g_Yuf2[NN*HH], g_Yuf3[NN*HH];
__device__ float g_Ywc1[NN*HH], g_Ywc2[NN*HH], g_Ywc3[NN*HH];
__device__ float g_x1p[NN*HH], g_x1s[NN*HH];
__device__ float g_h1p[NN*HH], g_h1s[NN*HH], g_h1e[NN*HH];
__device__ float g_P1[NN*HH], g_P2[NN*HH], g_E3[NN*HH];
__device__ float g_A1[NN*HH], g_A2[NN*HH], g_A3[NN*HH];
__device__ float g_c1o[NN*HH], g_c2o[NN*HH], g_c3o[NN*HH];
__device__ float g_y2p[NN], g_y2s[NN], g_lam1[NN], g_lam2[NN];
__device__ float g_Z1[NN*H3], g_Z2[NN*H3], g_Z3[NN*H3];

// ----------------------------- helpers -----------------------------
__device__ __forceinline__ float wred(float s){
  #pragma unroll
  for(int o=16;o;o>>=1) s += __shfl_xor_sync(0xffffffffu, s, o);
  return s;
}
template<int R> __device__ __forceinline__ float wdot(const float* a, const float* b){
  float s=0.f;
  #pragma unroll
  for(int i=0;i<R;i++) s += a[i]*b[i];
  return wred(s);
}
template<int R> __device__ __forceinline__ float wnrm(const float* a){
  return sqrtf(wdot<R>(a,a) + 1e-15f);
}
__device__ __forceinline__ float atanh_c(float u){
  u = fminf(fmaxf(u, -1.0f+1e-5f), 1.0f-1e-5f);
  return atanhf(u);
}
__device__ __forceinline__ float tan_c(float u){
  u = fminf(fmaxf(u, -1.47079f), 1.47079f);
  return tanf(u);
}
__device__ __forceinline__ float safe_den(float d){
  return d >= 0.f ? fmaxf(d, EPSF) : fminf(d, -EPSF);
}
__device__ __forceinline__ void ld4(float* v, const float* p){
  float4 t = *(const float4*)p; v[0]=t.x; v[1]=t.y; v[2]=t.z; v[3]=t.w;
}
__device__ __forceinline__ void st4(float* p, const float* v){
  *(float4*)p = make_float4(v[0],v[1],v[2],v[3]);
}
__device__ __forceinline__ void cp4(float* d, const float* s){
  #pragma unroll
  for(int i=0;i<4;i++) d[i]=s[i];
}
template<int R> __device__ __forceinline__ void sigm(float* v){
  #pragma unroll
  for(int i=0;i<R;i++) v[i] = 1.f/(1.f+expf(-v[i]));
}
template<int R> __device__ __forceinline__ void tanhv(float* v){
  #pragma unroll
  for(int i=0;i<R;i++) v[i] = tanhf(v[i]);
}
template<int R> __device__ __forceinline__ void proj_p(float* v){
  float n = wnrm<R>(v);
  if(n > PMF){
    float s = PMF/n;
    #pragma unroll
    for(int i=0;i<R;i++) v[i]*=s;
  }
}
template<int R> __device__ __forceinline__ void expmap0_p(float* v){
  float n = wnrm<R>(v); float s = tanhf(n)/n;
  #pragma unroll
  for(int i=0;i<R;i++) v[i]*=s;
  proj_p<R>(v);
}
template<int R> __device__ __forceinline__ void logmap0_p(float* v){
  float n = wnrm<R>(v); float s = atanh_c(n)/n;
  #pragma unroll
  for(int i=0;i<R;i++) v[i]*=s;
}
template<int R> __device__ __forceinline__ void expmap0_s(float* v){
  float n = wnrm<R>(v); float s = tan_c(n)/n;
  #pragma unroll
  for(int i=0;i<R;i++) v[i]*=s;
}
template<int R> __device__ __forceinline__ void logmap0_s(float* v){
  float n = wnrm<R>(v); float s = atanf(n)/n;
  #pragma unroll
  for(int i=0;i<R;i++) v[i]*=s;
}
template<int R> __device__ __forceinline__ void smul_p(float r, float* v){
  float n = wnrm<R>(v); float s = tanhf(r*atanh_c(n))/n;
  #pragma unroll
  for(int i=0;i<R;i++) v[i]*=s;
  proj_p<R>(v);
}
template<int R> __device__ __forceinline__ void smul_s(float r, float* v){
  float n = wnrm<R>(v); float s = tan_c(r*atanf(n))/n;
  #pragma unroll
  for(int i=0;i<R;i++) v[i]*=s;
}
template<int R> __device__ __forceinline__ void madd_p(const float* x, const float* y, float* o){
  float x2 = wdot<R>(x,x), y2 = wdot<R>(y,y), xy = wdot<R>(x,y);
  float cx = 1.f + 2.f*xy + y2;
  float cy = 1.f - x2;
  float dn = safe_den(1.f + 2.f*xy + x2*y2);
  #pragma unroll
  for(int i=0;i<R;i++) o[i] = (cx*x[i] + cy*y[i])/dn;
  proj_p<R>(o);
}
template<int R> __device__ __forceinline__ void madd_s(const float* x, const float* y, float* o){
  float x2 = wdot<R>(x,x), y2 = wdot<R>(y,y), xy = wdot<R>(x,y);
  float cx = 1.f - 2.f*xy - y2;
  float cy = 1.f + x2;
  float dn = safe_den(1.f - 2.f*xy + x2*y2);
  #pragma unroll
  for(int i=0;i<R;i++) o[i] = (cx*x[i] + cy*y[i])/dn;
}
template<int R> __device__ __forceinline__ void pwmul_p(const float* w, const float* x, float* o){
  float wx[R];
  #pragma unroll
  for(int i=0;i<R;i++) wx[i] = w[i]*x[i];
  float nx = wnrm<R>(x), nwx = wnrm<R>(wx);
  float s = tanhf(nwx/nx*atanh_c(nx))/nwx;
  #pragma unroll
  for(int i=0;i<R;i++) o[i] = wx[i]*s;
  proj_p<R>(o);
}
template<int R> __device__ __forceinline__ void pwmul_s(const float* w, const float* x, float* o){
  float wx[R];
  #pragma unroll
  for(int i=0;i<R;i++) wx[i] = w[i]*x[i];
  float nx = wnrm<R>(x), nwx = wnrm<R>(wx);
  float s = tan_c(nwx/nx*atanf(nx))/nwx;
  #pragma unroll
  for(int i=0;i<R;i++) o[i] = wx[i]*s;
}
template<int R> __device__ __forceinline__ void pwmulg_p(const float* w, float g, float* o){
  float wx[R];
  #pragma unroll
  for(int i=0;i<R;i++) wx[i] = w[i]*g;
  float nx = sqrtf(g*g + 1e-15f), nwx = wnrm<R>(wx);
  float s = tanhf(nwx/nx*atanh_c(nx))/nwx;
  #pragma unroll
  for(int i=0;i<R;i++) o[i] = wx[i]*s;
  proj_p<R>(o);
}
template<int R> __device__ __forceinline__ void pwmulg_s(const float* w, float g, float* o){
  float wx[R];
  #pragma unroll
  for(int i=0;i<R;i++) wx[i] = w[i]*g;
  float nx = sqrtf(g*g + 1e-15f), nwx = wnrm<R>(wx);
  float s = tan_c(nwx/nx*atanf(nx))/nwx;
  #pragma unroll
  for(int i=0;i<R;i++) o[i] = wx[i]*s;
}
__device__ __forceinline__ void wmid3_p(const float* a, const float* b, const float* c, float* o){
  float la = 2.f/(1.f - wdot<4>(a,a));
  float lb = 2.f/(1.f - wdot<4>(b,b));
  float lc = 2.f/(1.f - wdot<4>(c,c));
  float den = fmaxf(fabsf(la+lb+lc-3.f), EPSF);
  #pragma unroll
  for(int i=0;i<4;i++) o[i] = (la*a[i]+lb*b[i]+lc*c[i])/den;
  smul_p<4>(0.5f, o);
}
__device__ __forceinline__ void softmax8(float* s){
  float m = s[0];
  #pragma unroll
  for(int k=1;k<8;k++) m = fmaxf(m, s[k]);
  float sum = 0.f;
  #pragma unroll
  for(int k=0;k<8;k++){ s[k] = expf(s[k]-m); sum += s[k]; }
  float inv = 1.f/sum;
  #pragma unroll
  for(int k=0;k<8;k++) s[k] *= inv;
}

// ----------------------------- bf16 3-term mma GEMM -----------------------------
__device__ __forceinline__ uint32_t pack_bf2(float f0, float f1){
  __nv_bfloat16 b0 = __float2bfloat16_rn(f0);
  __nv_bfloat16 b1 = __float2bfloat16_rn(f1);
  return ((uint32_t)__bfloat16_as_ushort(b1)<<16) | (uint32_t)__bfloat16_as_ushort(b0);
}
__device__ __forceinline__ void split_bf2(float f0, float f1, uint32_t& hi, uint32_t& lo){
  __nv_bfloat16 b0 = __float2bfloat16_rn(f0);
  __nv_bfloat16 b1 = __float2bfloat16_rn(f1);
  hi = ((uint32_t)__bfloat16_as_ushort(b1)<<16) | (uint32_t)__bfloat16_as_ushort(b0);
  lo = pack_bf2(f0 - __bfloat162float(b0), f1 - __bfloat162float(b1));
}
__device__ __forceinline__ void mma16(float* d, const uint32_t* a, const uint32_t* b){
  asm volatile("mma.sync.aligned.m16n8k16.row.col.f32.bf16.bf16.f32 "
    "{%0,%1,%2,%3},{%4,%5,%6,%7},{%8,%9},{%0,%1,%2,%3};"
    : "+f"(d[0]),"+f"(d[1]),"+f"(d[2]),"+f"(d[3])
    : "r"(a[0]),"r"(a[1]),"r"(a[2]),"r"(a[3]),"r"(b[0]),"r"(b[1]));
}

// C[m0:m0+64, n0:n0+128] = A[.,128] @ W[n,128]^T + bias
__device__ __forceinline__ void gemm_mma(const float* __restrict__ A, const float* __restrict__ W,
                                         const float* __restrict__ bias, float* __restrict__ C, int HO){
  extern __shared__ uint32_t sh[];
  uint32_t* Ah = sh;                 // [64][PADU]
  uint32_t* Al = sh + 64*PADU;
  uint32_t* Bh = sh + 128*PADU;      // [128][PADU]
  uint32_t* Bl = sh + 256*PADU;
  const int m0 = blockIdx.x*64;
  const int n0 = blockIdx.y*128;
  const int t = threadIdx.x;
  const int lane = t & 31, w = t >> 5;
  const int wm = w >> 2, wn = w & 3;
  const int gid = lane >> 2, tig = lane & 3;

  #pragma unroll
  for(int i=0;i<16;i++){
    int p = t + i*256; int r = p>>6, c = p&63;
    float2 v = *(const float2*)(A + (m0+r)*128 + c*2);
    uint32_t hi, lo; split_bf2(v.x, v.y, hi, lo);
    Ah[r*PADU+c]=hi; Al[r*PADU+c]=lo;
  }
  #pragma unroll
  for(int i=0;i<32;i++){
    int p = t + i*256; int r = p>>6, c = p&63;
    float2 v = *(const float2*)(W + (n0+r)*128 + c*2);
    uint32_t hi, lo; split_bf2(v.x, v.y, hi, lo);
    Bh[r*PADU+c]=hi; Bl[r*PADU+c]=lo;
  }
  __syncthreads();

  float acc[2][4][4];
  #pragma unroll
  for(int mt=0;mt<2;mt++)
    #pragma unroll
    for(int nt=0;nt<4;nt++)
      #pragma unroll
      for(int i=0;i<4;i++) acc[mt][nt][i]=0.f;

  #pragma unroll
  for(int s=0;s<8;s++){
    int k2 = s*8;
    uint32_t ah[2][4], al[2][4];
    #pragma unroll
    for(int mt=0;mt<2;mt++){
      int r = wm*32 + mt*16 + gid;
      ah[mt][0]=Ah[r*PADU+k2+tig];     al[mt][0]=Al[r*PADU+k2+tig];
      ah[mt][1]=Ah[(r+8)*PADU+k2+tig]; al[mt][1]=Al[(r+8)*PADU+k2+tig];
      ah[mt][2]=Ah[r*PADU+k2+tig+4];   al[mt][2]=Al[r*PADU+k2+tig+4];
      ah[mt][3]=Ah[(r+8)*PADU+k2+tig+4]; al[mt][3]=Al[(r+8)*PADU+k2+tig+4];
    }
    uint32_t bh[4][2], bl[4][2];
    #pragma unroll
    for(int nt=0;nt<4;nt++){
      int nr = wn*32 + nt*8 + gid;
      bh[nt][0]=Bh[nr*PADU+k2+tig];   bl[nt][0]=Bl[nr*PADU+k2+tig];
      bh[nt][1]=Bh[nr*PADU+k2+tig+4]; bl[nt][1]=Bl[nr*PADU+k2+tig+4];
    }
    #pragma unroll
    for(int mt=0;mt<2;mt++)
      #pragma unroll
      for(int nt=0;nt<4;nt++){
        mma16(acc[mt][nt], al[mt], bh[nt]);
        mma16(acc[mt][nt], ah[mt], bl[nt]);
        mma16(acc[mt][nt], ah[mt], bh[nt]);
      }
  }

  #pragma unroll
  for(int mt=0;mt<2;mt++){
    int r = m0 + wm*32 + mt*16 + gid;
    #pragma unroll
    for(int nt=0;nt<4;nt++){
      int c = n0 + wn*32 + nt*8 + tig*2;
      float b0 = bias[c], b1 = bias[c+1];
      *(float2*)(C + r*HO + c)     = make_float2(acc[mt][nt][0]+b0, acc[mt][nt][1]+b1);
      *(float2*)(C + (r+8)*HO + c) = make_float2(acc[mt][nt][2]+b0, acc[mt][nt][3]+b1);
    }
  }
}

struct GArgs {
  const float* x; const float* h3; const float* c3;
  const float* Wq; const float* bq; const float* Wc; const float* bc;
  const float* Uf; const float* bf; const float* Up; const float* bp;
};

__global__ void __launch_bounds__(256) k_gemm1(GArgs ga){
  const float* A; const float* W; const float* B; float* C;
  switch(blockIdx.z){
    case 0: A=ga.x;   W=ga.Wq; B=ga.bq; C=g_Yq;   break;
    case 1: A=g_l1;   W=ga.Up; B=ga.bp; C=g_Yup1; break;
    case 2: A=g_l2;   W=ga.Up; B=ga.bp; C=g_Yup2; break;
    case 3: A=ga.h3;  W=ga.Up; B=ga.bp; C=g_Yup3; break;
    case 4: A=g_l1;   W=ga.Uf; B=ga.bf; C=g_Yuf1; break;
    case 5: A=g_l2;   W=ga.Uf; B=ga.bf; C=g_Yuf2; break;
    case 6: A=ga.h3;  W=ga.Uf; B=ga.bf; C=g_Yuf3; break;
    case 7: A=g_lc1;  W=ga.Wc; B=ga.bc; C=g_Ywc1; break;
    case 8: A=g_lc2;  W=ga.Wc; B=ga.bc; C=g_Ywc2; break;
    default:A=ga.c3;  W=ga.Wc; B=ga.bc; C=g_Ywc3; break;
  }
  gemm_mma(A, W, B, C, 128);
}

__global__ void __launch_bounds__(256) k_gemm2(const float* __restrict__ W, const float* __restrict__ B){
  const float* A; float* C;
  switch(blockIdx.z){
    case 0: A=g_A1; C=g_Z1; break;
    case 1: A=g_A2; C=g_Z2; break;
    default:A=g_A3; C=g_Z3; break;
  }
  gemm_mma(A, W, B, C, 384);
}

// ----------------------------- prep -----------------------------
__global__ void k_prep(const float* __restrict__ h1, const float* __restrict__ c1,
                       const float* __restrict__ h2, const float* __restrict__ c2){
  int n = (blockIdx.x*blockDim.x + threadIdx.x) >> 5;
  if(n >= NN) return;
  int l = threadIdx.x & 31;
  int b = n*128 + l*4;
  float v[4];
  ld4(v, h1+b); logmap0_p<4>(v); st4(g_l1+b, v);
  ld4(v, h2+b); logmap0_s<4>(v); st4(g_l2+b, v);
  ld4(v, c1+b); logmap0_p<4>(v); st4(g_lc1+b, v);
  ld4(v, c2+b); logmap0_s<4>(v); st4(g_lc2+b, v);
}

// ----------------------------- per-node elementwise -----------------------------
__global__ void k_node(const float* __restrict__ h1, const float* __restrict__ h2,
                       const float* __restrict__ h3, const float* __restrict__ c1,
                       const float* __restrict__ c2, const float* __restrict__ c3,
                       const float* __restrict__ del_t, const float* __restrict__ dptr){
  int n = (blockIdx.x*blockDim.x + threadIdx.x) >> 5;
  if(n >= NN) return;
  int l = threadIdx.x & 31;
  int b = n*128 + l*4;

  float yq[4]; ld4(yq, g_Yq+b);
  float v[4];
  cp4(v, yq); expmap0_p<4>(v); st4(g_x1p+b, v);
  cp4(v, yq); expmap0_s<4>(v); st4(g_x1s+b, v);

  float s1[4]; ld4(s1, g_Yup1+b); expmap0_p<4>(s1); sigm<4>(s1); logmap0_p<4>(s1);
  float s2[4]; ld4(s2, g_Yup2+b); expmap0_s<4>(s2); sigm<4>(s2); logmap0_s<4>(s2);
  float s3[4]; ld4(s3, g_Yup3+b); sigm<4>(s3);

  float h1v[4]; ld4(h1v, h1+b);
  float h2v[4]; ld4(h2v, h2+b);
  float h3v[4]; ld4(h3v, h3+b);
  float l1v[4]; ld4(l1v, g_l1+b);

  // Poincare h-branch
  float ht1p[4]; pwmul_p<4>(s1, h1v, ht1p);
  float tmp[4];
  cp4(tmp, h2v); logmap0_s<4>(tmp); expmap0_p<4>(tmp);
  float ht2p[4]; pwmul_p<4>(s2, tmp, ht2p);
  cp4(tmp, h3v); expmap0_p<4>(tmp);
  float ht3p[4]; pwmul_p<4>(s3, tmp, ht3p);
  float h1pv[4]; wmid3_p(ht1p, ht2p, ht3p, h1pv);
  #pragma unroll
  for(int i=0;i<4;i++) h1pv[i] *= 3.f;
  st4(g_h1p+b, h1pv);
  float y2p = wdot<4>(h1pv, h1pv);
  if(l==0) g_y2p[n] = y2p;

  // Sphere h-branch
  cp4(tmp, l1v); expmap0_s<4>(tmp);
  float ht1s[4]; pwmul_p<4>(s1, tmp, ht1s);
  float ht2s[4]; pwmul_s<4>(s2, h2v, ht2s);
  cp4(tmp, h3v); expmap0_s<4>(tmp);
  float ht3s[4]; pwmul_s<4>(s3, tmp, ht3s);
  float h1sv[4]; wmid3_p(ht1s, ht2s, ht3s, h1sv);
  #pragma unroll
  for(int i=0;i<4;i++) h1sv[i] *= 3.f;
  st4(g_h1s+b, h1sv);
  float y2s = wdot<4>(h1sv, h1sv);
  if(l==0) g_y2s[n] = y2s;

  // Euclid h-branch
  float e1[4]; cp4(e1, ht1p); logmap0_p<4>(e1);
  float e2[4]; cp4(e2, ht2s); logmap0_s<4>(e2);
  float h1ev[4];
  #pragma unroll
  for(int i=0;i<4;i++) h1ev[i] = e1[i] + e2[i] + s3[i]*h3v[i];
  st4(g_h1e+b, h1ev);

  float g = dptr[0] / (del_t[n] + 1.f);

  // Poincare cell
  float c1v[4]; ld4(c1v, c1+b);
  float cskp[4]; ld4(cskp, g_Ywc1+b);
  expmap0_p<4>(cskp); logmap0_p<4>(cskp); tanhv<4>(cskp); expmap0_p<4>(cskp);
  float nk[4];
  #pragma unroll
  for(int i=0;i<4;i++) nk[i] = -cskp[i];
  float t1[4]; madd_p<4>(nk, c1v, t1);
  float t2[4]; pwmulg_p<4>(cskp, g, t2);
  float cktp[4]; madd_p<4>(t1, t2, cktp);
  float fp[4]; ld4(fp, g_Yuf1+b); expmap0_p<4>(fp); logmap0_p<4>(fp); sigm<4>(fp);
  float P1[4]; pwmul_p<4>(fp, cktp, P1);
  st4(g_P1+b, P1);
  float lam1 = 2.f/(1.f - wdot<4>(P1,P1));
  if(l==0) g_lam1[n] = lam1;

  // Sphere cell
  float c2v[4]; ld4(c2v, c2+b);
  float csks[4]; ld4(csks, g_Ywc2+b);
  expmap0_s<4>(csks); logmap0_s<4>(csks); tanhv<4>(csks); expmap0_s<4>(csks);
  #pragma unroll
  for(int i=0;i<4;i++) nk[i] = -csks[i];
  madd_s<4>(nk, c2v, t1);
  pwmulg_s<4>(csks, g, t2);
  float ckts[4]; madd_s<4>(t1, t2, ckts);
  float fs[4]; ld4(fs, g_Yuf2+b); expmap0_s<4>(fs); logmap0_s<4>(fs); sigm<4>(fs);
  float P2[4]; pwmul_s<4>(fs, ckts, P2);
  st4(g_P2+b, P2);
  float lam2 = 2.f/(1.f + wdot<4>(P2,P2));
  if(l==0) g_lam2[n] = lam2;

  // Euclid cell
  float c3v[4]; ld4(c3v, c3+b);
  float cske[4]; ld4(cske, g_Ywc3+b); tanhv<4>(cske);
  float fe[4]; ld4(fe, g_Yuf3+b); sigm<4>(fe);
  float E3[4];
  #pragma unroll
  for(int i=0;i<4;i++) E3[i] = fe[i]*(c3v[i] - cske[i] + cske[i]*g);
  st4(g_E3+b, E3);
}

// ----------------------------- gather + attention + cell reductions -----------------------------
__global__ void k_attn(const int* __restrict__ nbr){
  int n = (blockIdx.x*blockDim.x + threadIdx.x) >> 5;
  if(n >= NN) return;
  int l = threadIdx.x & 31;
  int b = n*128 + l*4;
  const int* nb = nbr + n*8;
  int j8[8], nj[8];
  #pragma unroll
  for(int k=0;k<8;k++){ j8[k] = nb[k]; nj[k] = j8[k]*128 + l*4; }

  float hk[8][4], sc[8], y2[8];

  // ---- Poincare attention -> g_A1 = logmap0_p(proj(smul_p(0.5, wmid)))
  {
    float xq[4]; ld4(xq, g_x1p+b);
    float x2 = wdot<4>(xq,xq);
    #pragma unroll
    for(int k=0;k<8;k++){
      ld4(hk[k], g_h1p + nj[k]);
      y2[k] = g_y2p[j8[k]];
      float s = 0.f;
      #pragma unroll
      for(int i=0;i<4;i++) s -= xq[i]*hk[k][i];
      float xy = wred(s);
      float cx = 1.f + 2.f*xy + y2[k];
      float cy = 1.f - x2;
      float dn = safe_den(1.f + 2.f*xy + x2*y2[k]);
      float o2 = cx*cx*x2 + 2.f*cx*cy*xy + cy*cy*y2[k];
      float nr = fminf(sqrtf(fmaxf(o2, 0.f) + 1e-15f)/fabsf(dn), PMF);
      sc[k] = -2.f*atanh_c(nr);
    }
    softmax8(sc);
    float num[4] = {0,0,0,0};
    float ds = 0.f;
    #pragma unroll
    for(int k=0;k<8;k++){
      float lam = 2.f/(1.f - y2[k]);
      float wk = sc[k]*lam;
      #pragma unroll
      for(int i=0;i<4;i++) num[i] += wk*hk[k][i];
      ds += sc[k]*(lam - 1.f);
    }
    float den = fmaxf(fabsf(ds), EPSF);
    float nrm = sqrtf(wdot<4>(num,num)/(den*den) + 1e-15f);
    float m = fminf(tanhf(0.5f*atanh_c(nrm)), PMF);
    float st = atanh_c(m)/(nrm*den);
    #pragma unroll
    for(int i=0;i<4;i++) num[i] *= st;
    st4(g_A1+b, num);
  }

  // ---- Sphere attention -> g_A2 = logmap0_s(smul_s(0.5, wmid))
  {
    float xq[4]; ld4(xq, g_x1s+b);
    float x2 = wdot<4>(xq,xq);
    #pragma unroll
    for(int k=0;k<8;k++){
      ld4(hk[k], g_h1s + nj[k]);
      y2[k] = g_y2s[j8[k]];
      float s = 0.f;
      #pragma unroll
      for(int i=0;i<4;i++) s -= xq[i]*hk[k][i];
      float xy = wred(s);
      float cx = 1.f - 2.f*xy - y2[k];
      float cy = 1.f + x2;
      float dn = safe_den(1.f - 2.f*xy + x2*y2[k]);
      float o2 = cx*cx*x2 + 2.f*cx*cy*xy + cy*cy*y2[k];
      float nr = sqrtf(fmaxf(o2, 0.f) + 1e-15f)/fabsf(dn);
      sc[k] = -2.f*atanf(nr);
    }
    softmax8(sc);
    float num[4] = {0,0,0,0};
    float ds = 0.f;
    #pragma unroll
    for(int k=0;k<8;k++){
      float lam = 2.f/(1.f + y2[k]);
      float wk = sc[k]*lam;
      #pragma unroll
      for(int i=0;i<4;i++) num[i] += wk*hk[k][i];
      ds += sc[k]*(lam - 1.f);
    }
    float den = fmaxf(fabsf(ds), EPSF);
    float nrm = sqrtf(wdot<4>(num,num)/(den*den) + 1e-15f);
    float m = tan_c(0.5f*atanf(nrm));
    float st = atanf(m)/(nrm*den);
    #pragma unroll
    for(int i=0;i<4;i++) num[i] *= st;
    st4(g_A2+b, num);
  }

  // ---- Euclid attention -> g_A3
  {
    float xq[4]; ld4(xq, g_Yq+b);
    const float isq = 0.08838834764831845f;
    #pragma unroll
    for(int k=0;k<8;k++){
      ld4(hk[k], g_h1e + nj[k]);
      sc[k] = wdot<4>(hk[k], xq) * isq;
    }
    softmax8(sc);
    float num[4] = {0,0,0,0};
    #pragma unroll
    for(int k=0;k<8;k++){
      #pragma unroll
      for(int i=0;i<4;i++) num[i] += sc[k]*hk[k][i];
    }
    st4(g_A3+b, num);
  }

  // ---- Poincare cell reduction -> g_c1o = smul_p(0.5, num/den)
  {
    float num[4] = {0,0,0,0};
    float ds = 0.f;
    #pragma unroll
    for(int k=0;k<8;k++){
      float pv[4]; ld4(pv, g_P1 + nj[k]);
      float lam = g_lam1[j8[k]];
      #pragma unroll
      for(int i=0;i<4;i++) num[i] += lam*pv[i];
      ds += lam - 1.f;
    }
    float den = fmaxf(fabsf(ds), EPSF);
    float nrm = sqrtf(wdot<4>(num,num)/(den*den) + 1e-15f);
    float m = fminf(tanhf(0.5f*atanh_c(nrm)), PMF);
    float st = m/(nrm*den);
    #pragma unroll
    for(int i=0;i<4;i++) num[i] *= st;
    st4(g_c1o+b, num);
  }
  // ---- Sphere cell reduction -> g_c2o
  {
    float num[4] = {0,0,0,0};
    float ds = 0.f;
    #pragma unroll
    for(int k=0;k<8;k++){
      float pv[4]; ld4(pv, g_P2 + nj[k]);
      float lam = g_lam2[j8[k]];
      #pragma unroll
      for(int i=0;i<4;i++) num[i] += lam*pv[i];
      ds += lam - 1.f;
    }
    float den = fmaxf(fabsf(ds), EPSF);
    float nrm = sqrtf(wdot<4>(num,num)/(den*den) + 1e-15f);
    float m = tan_c(0.5f*atanf(nrm));
    float st = m/(nrm*den);
    #pragma unroll
    for(int i=0;i<4;i++) num[i] *= st;
    st4(g_c2o+b, num);
  }
  // ---- Euclid cell sum
  {
    float acc[4] = {0,0,0,0};
    #pragma unroll
    for(int k=0;k<8;k++){
      float ev[4]; ld4(ev, g_E3 + nj[k]);
      #pragma unroll
      for(int i=0;i<4;i++) acc[i] += ev[i];
    }
    st4(g_c3o+b, acc);
  }
}

// ----------------------------- final epilogue -----------------------------
__global__ void k_final(const float* __restrict__ iou1, const float* __restrict__ iou2,
                        const float* __restrict__ iou3, float* __restrict__ out){
  int n = (blockIdx.x*blockDim.x + threadIdx.x) >> 5;
  if(n >= NN) return;
  int l = threadIdx.x & 31;
  int b = n*128 + l*4;
  int b3 = n*384 + l*4;

  // Poincare
  {
    float z[12], io[12];
    #pragma unroll
    for(int c=0;c<3;c++){ ld4(z+4*c, g_Z1 + b3 + 128*c); ld4(io+4*c, iou1 + b3 + 128*c); }
    expmap0_p<12>(z);
    float ni[12]; madd_p<12>(io, z, ni);
    float ip[4], op[4], up[4];
    cp4(ip, ni+0); logmap0_p<4>(ip); sigm<4>(ip);
    cp4(op, ni+4); logmap0_p<4>(op); sigm<4>(op);
    cp4(up, ni+8); logmap0_p<4>(up); tanhv<4>(up);
    float t[4]; pwmul_p<4>(ip, up, t);
    float cc[4]; ld4(cc, g_c1o+b);
    float nc[4]; madd_p<4>(t, cc, nc);
    float lt[4]; cp4(lt, nc); logmap0_p<4>(lt); tanhv<4>(lt);
    float nh[4]; pwmul_p<4>(op, lt, nh);
    st4(out + 0*NN*128 + b, nh);
    st4(out + 1*NN*128 + b, nc);
  }
  // Sphere
  {
    float z[12], io[12];
    #pragma unroll
    for(int c=0;c<3;c++){ ld4(z+4*c, g_Z2 + b3 + 128*c); ld4(io+4*c, iou2 + b3 + 128*c); }
    expmap0_s<12>(z);
    float ni[12]; madd_s<12>(io, z, ni);
    float ip[4], op[4], up[4];
    cp4(ip, ni+0); logmap0_s<4>(ip); sigm<4>(ip);
    cp4(op, ni+4); logmap0_s<4>(op); sigm<4>(op);
    cp4(up, ni+8); logmap0_s<4>(up); tanhv<4>(up);
    float t[4]; pwmul_s<4>(ip, up, t);
    float cc[4]; ld4(cc, g_c2o+b);
    float nc[4]; madd_s<4>(t, cc, nc);
    float lt[4]; cp4(lt, nc); logmap0_s<4>(lt); tanhv<4>(lt);
    float nh[4]; pwmul_s<4>(op, lt, nh);
    st4(out + 2*NN*128 + b, nh);
    st4(out + 3*NN*128 + b, nc);
  }
  // Euclid
  {
    float z[12], io[12];
    #pragma unroll
    for(int c=0;c<3;c++){ ld4(z+4*c, g_Z3 + b3 + 128*c); ld4(io+4*c, iou3 + b3 + 128*c); }
    float ip[4], op[4], up[4];
    #pragma unroll
    for(int i=0;i<4;i++){
      ip[i] = io[i]   + z[i];
      op[i] = io[4+i] + z[4+i];
      up[i] = io[8+i] + z[8+i];
    }
    sigm<4>(ip); sigm<4>(op); tanhv<4>(up);
    float cc[4]; ld4(cc, g_c3o+b);
    float nc[4], nh[4];
    #pragma unroll
    for(int i=0;i<4;i++){
      nc[i] = ip[i]*up[i] + cc[i];
      nh[i] = op[i]*tanhf(nc[i]);
    }
    st4(out + 4*NN*128 + b, nh);
    st4(out + 5*NN*128 + b, nc);
  }
}

// ----------------------------- launch -----------------------------
extern "C" void kernel_launch(void* const* d_in, const int* in_sizes, int n_in,
                              void* d_out, int out_size){
  const float* x     = (const float*)d_in[0];
  const float* h1    = (const float*)d_in[1];
  const float* c1    = (const float*)d_in[2];
  const float* h2    = (const float*)d_in[3];
  const float* c2    = (const float*)d_in[4];
  const float* h3    = (const float*)d_in[5];
  const float* c3    = (const float*)d_in[6];
  const float* del_t = (const float*)d_in[7];
  const float* iou1  = (const float*)d_in[8];
  const float* iou2  = (const float*)d_in[9];
  const float* iou3  = (const float*)d_in[10];
  const float* Wq_w  = (const float*)d_in[11];
  const float* Wq_b  = (const float*)d_in[12];
  const float* Wc_w  = (const float*)d_in[13];
  const float* Wc_b  = (const float*)d_in[14];
  const float* Uf_w  = (const float*)d_in[15];
  const float* Uf_b  = (const float*)d_in[16];
  const float* Up_w  = (const float*)d_in[17];
  const float* Up_b  = (const float*)d_in[18];
  const float* Uiou_w= (const float*)d_in[19];
  const float* Uiou_b= (const float*)d_in[20];
  const float* dptr  = (const float*)d_in[21];
  const int*   nbr   = (const int*)d_in[22];
  float* out = (float*)d_out;

  cudaFuncSetAttribute(k_gemm1, cudaFuncAttributeMaxDynamicSharedMemorySize, GSMEM);
  cudaFuncSetAttribute(k_gemm2, cudaFuncAttributeMaxDynamicSharedMemorySize, GSMEM);

  k_prep<<<NN/8, 256>>>(h1, c1, h2, c2);

  GArgs ga;
  ga.x = x; ga.h3 = h3; ga.c3 = c3;
  ga.Wq = Wq_w; ga.bq = Wq_b;
  ga.Wc = Wc_w; ga.bc = Wc_b;
  ga.Uf = Uf_w; ga.bf = Uf_b;
  ga.Up = Up_w; ga.bp = Up_b;
  k_gemm1<<<dim3(NN/64, 1, 10), 256, GSMEM>>>(ga);

  k_node<<<NN/8, 256>>>(h1, h2, h3, c1, c2, c3, del_t, dptr);
  k_attn<<<NN/8, 256>>>(nbr);
  k_gemm2<<<dim3(NN/64, 3, 3), 256, GSMEM>>>(Uiou_w, Uiou_b);
  k_final<<<NN/8, 256>>>(iou1, iou2, iou3, out);
}

// round 6
// speedup vs baseline: 1.9761x; 1.2017x over previous
#include <cuda_runtime.h>
#include <cuda_bf16.h>
#include <math.h>
#include <stdint.h>

#define NN 8192
#define HH 128
#define H3 384
#define EPSF 1e-6f
#define PMF 0.9999f
#define PADU 68
#define GSMEM (384 * PADU * 4)

// ----------------------------- fp32 scratch -----------------------------
__device__ float g_l1[NN*HH];
__device__ float g_Yq[NN*HH];
__device__ float g_Yup1[NN*HH], g_Yup2[NN*HH], g_Yup3[NN*HH];
__device__ float g_Yuf1[NN*HH], g_Yuf2[NN*HH], g_Yuf3[NN*HH];
__device__ float g_Ywc1[NN*HH], g_Ywc2[NN*HH], g_Ywc3[NN*HH];
__device__ float g_x1p[NN*HH], g_x1s[NN*HH];
__device__ float g_h1p[NN*HH], g_h1s[NN*HH], g_h1e[NN*HH];
__device__ float g_P1[NN*HH], g_P2[NN*HH], g_E3[NN*HH];
__device__ float g_c1o[NN*HH], g_c2o[NN*HH], g_c3o[NN*HH];
__device__ float g_Z1[NN*H3], g_Z2[NN*H3], g_Z3[NN*H3];
// per-node scalars
__device__ float g_y2p[NN], g_y2s[NN], g_lam1[NN], g_lam2[NN];
__device__ float g_x2p[NN], g_x2s[NN];
__device__ float g_nh1[NN], g_nh2[NN];
__device__ float g_n2c1o[NN], g_n2c2o[NN];
// bf16 hi/lo packed (uint32 = bf16x2)
__device__ uint32_t g_xh[NN*64],  g_xl[NN*64];
__device__ uint32_t g_l1h[NN*64], g_l1l[NN*64];
__device__ uint32_t g_l2h[NN*64], g_l2l[NN*64];
__device__ uint32_t g_h3h[NN*64], g_h3l[NN*64];
__device__ uint32_t g_lc1h[NN*64], g_lc1l[NN*64];
__device__ uint32_t g_lc2h[NN*64], g_lc2l[NN*64];
__device__ uint32_t g_c3h[NN*64], g_c3l[NN*64];
__device__ uint32_t g_A1h[NN*64], g_A1l[NN*64];
__device__ uint32_t g_A2h[NN*64], g_A2l[NN*64];
__device__ uint32_t g_A3h[NN*64], g_A3l[NN*64];
__device__ uint32_t g_Wqh[128*64], g_Wql[128*64];
__device__ uint32_t g_Wch[128*64], g_Wcl[128*64];
__device__ uint32_t g_Ufh[128*64], g_Ufl[128*64];
__device__ uint32_t g_Uph[128*64], g_Upl[128*64];
__device__ uint32_t g_Uih[384*64], g_Uil[384*64];

// ----------------------------- fast math -----------------------------
__device__ __forceinline__ float ftanh(float x){
  float a = fabsf(x);
  float r;
  if(a < 0.105f){
    float a2 = a*a;
    r = a*(1.f - a2*(0.33333334f - a2*0.13333334f));
  } else {
    float t = __expf(-2.f*a);
    r = __fdividef(1.f - t, 1.f + t);
  }
  return copysignf(r, x);
}
__device__ __forceinline__ float fatanh(float u){
  u = fminf(fmaxf(u, -1.f + 1e-5f), 1.f - 1e-5f);
  float a = fabsf(u);
  float r;
  if(a < 0.105f){
    float a2 = a*a;
    r = a*(1.f + a2*(0.33333334f + a2*0.2f));
  } else {
    r = 0.5f*__logf(__fdividef(1.f + a, 1.f - a));
  }
  return copysignf(r, u);
}
__device__ __forceinline__ float fsig(float x){
  return __fdividef(1.f, 1.f + __expf(-x));
}
__device__ __forceinline__ float ftan(float u){
  u = fminf(fmaxf(u, -1.47079f), 1.47079f);
  return __tanf(u);
}
__device__ __forceinline__ float safe_den(float d){
  return d >= 0.f ? fmaxf(d, EPSF) : fminf(d, -EPSF);
}

// ----------------------------- warp helpers -----------------------------
__device__ __forceinline__ float wred(float s){
  #pragma unroll
  for(int o=16;o;o>>=1) s += __shfl_xor_sync(0xffffffffu, s, o);
  return s;
}
template<int R> __device__ __forceinline__ float wdot(const float* a, const float* b){
  float s=0.f;
  #pragma unroll
  for(int i=0;i<R;i++) s += a[i]*b[i];
  return wred(s);
}
__device__ __forceinline__ void ld4(float* v, const float* p){
  float4 t = *(const float4*)p; v[0]=t.x; v[1]=t.y; v[2]=t.z; v[3]=t.w;
}
__device__ __forceinline__ void st4(float* p, const float* v){
  *(float4*)p = make_float4(v[0],v[1],v[2],v[3]);
}

// pwmul with known ||x||, Poincare (clamped) — returns result norm
__device__ __forceinline__ float pwmulp_k(const float* w, const float* x, float nx, float* o){
  float wx[4];
  #pragma unroll
  for(int i=0;i<4;i++) wx[i] = w[i]*x[i];
  float nwx = sqrtf(wdot<4>(wx,wx) + 1e-15f);
  float m = fminf(ftanh(__fdividef(nwx,nx)*fatanh(nx)), PMF);
  float s = __fdividef(m, nwx);
  #pragma unroll
  for(int i=0;i<4;i++) o[i] = wx[i]*s;
  return m;
}
// pwmul with known ||x||, sphere — returns result norm
__device__ __forceinline__ float pwmuls_k(const float* w, const float* x, float nx, float* o){
  float wx[4];
  #pragma unroll
  for(int i=0;i<4;i++) wx[i] = w[i]*x[i];
  float nwx = sqrtf(wdot<4>(wx,wx) + 1e-15f);
  float m = ftan(__fdividef(nwx,nx)*atanf(nx));
  float s = __fdividef(m, nwx);
  #pragma unroll
  for(int i=0;i<4;i++) o[i] = wx[i]*s;
  return m;
}
__device__ __forceinline__ void softmax8(float* s){
  float m = s[0];
  #pragma unroll
  for(int k=1;k<8;k++) m = fmaxf(m, s[k]);
  float sum = 0.f;
  #pragma unroll
  for(int k=0;k<8;k++){ s[k] = __expf(s[k]-m); sum += s[k]; }
  float inv = __fdividef(1.f, sum);
  #pragma unroll
  for(int k=0;k<8;k++) s[k] *= inv;
}

// ----------------------------- bf16 packing -----------------------------
__device__ __forceinline__ uint32_t pack_bf2(float f0, float f1){
  __nv_bfloat16 b0 = __float2bfloat16_rn(f0);
  __nv_bfloat16 b1 = __float2bfloat16_rn(f1);
  return ((uint32_t)__bfloat16_as_ushort(b1)<<16) | (uint32_t)__bfloat16_as_ushort(b0);
}
__device__ __forceinline__ void split_bf2(float f0, float f1, uint32_t& hi, uint32_t& lo){
  __nv_bfloat16 b0 = __float2bfloat16_rn(f0);
  __nv_bfloat16 b1 = __float2bfloat16_rn(f1);
  hi = ((uint32_t)__bfloat16_as_ushort(b1)<<16) | (uint32_t)__bfloat16_as_ushort(b0);
  lo = pack_bf2(f0 - __bfloat162float(b0), f1 - __bfloat162float(b1));
}
__device__ __forceinline__ void pack_store(uint32_t* dh, uint32_t* dl, int idx, const float* v){
  uint32_t h0,l0,h1,l1;
  split_bf2(v[0],v[1],h0,l0);
  split_bf2(v[2],v[3],h1,l1);
  *(uint2*)(dh+idx) = make_uint2(h0,h1);
  *(uint2*)(dl+idx) = make_uint2(l0,l1);
}

// ----------------------------- GEMM (pre-packed bf16 3-term) -----------------------------
__device__ __forceinline__ void mma16(float* d, const uint32_t* a, const uint32_t* b){
  asm volatile("mma.sync.aligned.m16n8k16.row.col.f32.bf16.bf16.f32 "
    "{%0,%1,%2,%3},{%4,%5,%6,%7},{%8,%9},{%0,%1,%2,%3};"
    : "+f"(d[0]),"+f"(d[1]),"+f"(d[2]),"+f"(d[3])
    : "r"(a[0]),"r"(a[1]),"r"(a[2]),"r"(a[3]),"r"(b[0]),"r"(b[1]));
}

__device__ __forceinline__ void gemm_pk(const uint32_t* __restrict__ AhG, const uint32_t* __restrict__ AlG,
                                        const uint32_t* __restrict__ BhG, const uint32_t* __restrict__ BlG,
                                        const float* __restrict__ bias, float* __restrict__ C, int HO){
  extern __shared__ uint32_t sh[];
  uint32_t* Ah = sh;
  uint32_t* Al = sh + 64*PADU;
  uint32_t* Bh = sh + 128*PADU;
  uint32_t* Bl = sh + 256*PADU;
  const int m0 = blockIdx.x*64;
  const int n0 = blockIdx.y*128;
  const int t = threadIdx.x;
  const int lane = t & 31, w = t >> 5;
  const int wm = w >> 2, wn = w & 3;
  const int gid = lane >> 2, tig = lane & 3;

  #pragma unroll
  for(int i=0;i<4;i++){
    int p = t + i*256; int r = p>>4, c = (p&15)*4;
    *(uint4*)(Ah + r*PADU + c) = *(const uint4*)(AhG + (m0+r)*64 + c);
    *(uint4*)(Al + r*PADU + c) = *(const uint4*)(AlG + (m0+r)*64 + c);
  }
  #pragma unroll
  for(int i=0;i<8;i++){
    int p = t + i*256; int r = p>>4, c = (p&15)*4;
    *(uint4*)(Bh + r*PADU + c) = *(const uint4*)(BhG + (n0+r)*64 + c);
    *(uint4*)(Bl + r*PADU + c) = *(const uint4*)(BlG + (n0+r)*64 + c);
  }
  __syncthreads();

  float acc[2][4][4];
  #pragma unroll
  for(int mt=0;mt<2;mt++)
    #pragma unroll
    for(int nt=0;nt<4;nt++)
      #pragma unroll
      for(int i=0;i<4;i++) acc[mt][nt][i]=0.f;

  #pragma unroll
  for(int s=0;s<8;s++){
    int k2 = s*8;
    uint32_t ah[2][4], al[2][4];
    #pragma unroll
    for(int mt=0;mt<2;mt++){
      int r = wm*32 + mt*16 + gid;
      ah[mt][0]=Ah[r*PADU+k2+tig];       al[mt][0]=Al[r*PADU+k2+tig];
      ah[mt][1]=Ah[(r+8)*PADU+k2+tig];   al[mt][1]=Al[(r+8)*PADU+k2+tig];
      ah[mt][2]=Ah[r*PADU+k2+tig+4];     al[mt][2]=Al[r*PADU+k2+tig+4];
      ah[mt][3]=Ah[(r+8)*PADU+k2+tig+4]; al[mt][3]=Al[(r+8)*PADU+k2+tig+4];
    }
    uint32_t bh[4][2], bl[4][2];
    #pragma unroll
    for(int nt=0;nt<4;nt++){
      int nr = wn*32 + nt*8 + gid;
      bh[nt][0]=Bh[nr*PADU+k2+tig];   bl[nt][0]=Bl[nr*PADU+k2+tig];
      bh[nt][1]=Bh[nr*PADU+k2+tig+4]; bl[nt][1]=Bl[nr*PADU+k2+tig+4];
    }
    #pragma unroll
    for(int mt=0;mt<2;mt++)
      #pragma unroll
      for(int nt=0;nt<4;nt++){
        mma16(acc[mt][nt], al[mt], bh[nt]);
        mma16(acc[mt][nt], ah[mt], bl[nt]);
        mma16(acc[mt][nt], ah[mt], bh[nt]);
      }
  }

  #pragma unroll
  for(int mt=0;mt<2;mt++){
    int r = m0 + wm*32 + mt*16 + gid;
    #pragma unroll
    for(int nt=0;nt<4;nt++){
      int c = n0 + wn*32 + nt*8 + tig*2;
      float b0 = bias[c], b1 = bias[c+1];
      *(float2*)(C + r*HO + c)     = make_float2(acc[mt][nt][0]+b0, acc[mt][nt][1]+b1);
      *(float2*)(C + (r+8)*HO + c) = make_float2(acc[mt][nt][2]+b0, acc[mt][nt][3]+b1);
    }
  }
}

__global__ void __launch_bounds__(256) k_gemm1(const float* __restrict__ bq, const float* __restrict__ bc,
                                               const float* __restrict__ bf, const float* __restrict__ bp){
  const uint32_t *Ah,*Al,*Bh,*Bl; const float* B; float* C;
  switch(blockIdx.z){
    case 0: Ah=g_xh;  Al=g_xl;  Bh=g_Wqh; Bl=g_Wql; B=bq; C=g_Yq;   break;
    case 1: Ah=g_l1h; Al=g_l1l; Bh=g_Uph; Bl=g_Upl; B=bp; C=g_Yup1; break;
    case 2: Ah=g_l2h; Al=g_l2l; Bh=g_Uph; Bl=g_Upl; B=bp; C=g_Yup2; break;
    case 3: Ah=g_h3h; Al=g_h3l; Bh=g_Uph; Bl=g_Upl; B=bp; C=g_Yup3; break;
    case 4: Ah=g_l1h; Al=g_l1l; Bh=g_Ufh; Bl=g_Ufl; B=bf; C=g_Yuf1; break;
    case 5: Ah=g_l2h; Al=g_l2l; Bh=g_Ufh; Bl=g_Ufl; B=bf; C=g_Yuf2; break;
    case 6: Ah=g_h3h; Al=g_h3l; Bh=g_Ufh; Bl=g_Ufl; B=bf; C=g_Yuf3; break;
    case 7: Ah=g_lc1h;Al=g_lc1l;Bh=g_Wch; Bl=g_Wcl; B=bc; C=g_Ywc1; break;
    case 8: Ah=g_lc2h;Al=g_lc2l;Bh=g_Wch; Bl=g_Wcl; B=bc; C=g_Ywc2; break;
    default:Ah=g_c3h; Al=g_c3l; Bh=g_Wch; Bl=g_Wcl; B=bc; C=g_Ywc3; break;
  }
  gemm_pk(Ah, Al, Bh, Bl, B, C, 128);
}

__global__ void __launch_bounds__(256) k_gemm2(const float* __restrict__ bi){
  const uint32_t *Ah,*Al; float* C;
  switch(blockIdx.z){
    case 0: Ah=g_A1h; Al=g_A1l; C=g_Z1; break;
    case 1: Ah=g_A2h; Al=g_A2l; C=g_Z2; break;
    default:Ah=g_A3h; Al=g_A3l; C=g_Z3; break;
  }
  gemm_pk(Ah, Al, g_Uih, g_Uil, bi, C, 384);
}

// ----------------------------- weight conversion -----------------------------
__global__ void k_cvtw(const float* __restrict__ Wq, const float* __restrict__ Wc,
                       const float* __restrict__ Uf, const float* __restrict__ Up,
                       const float* __restrict__ Ui){
  int i = blockIdx.x*256 + threadIdx.x;
  const float* src; uint32_t *dh, *dl; int off;
  if(i < 8192){ src=Wq; dh=g_Wqh; dl=g_Wql; off=i; }
  else if(i < 16384){ src=Wc; dh=g_Wch; dl=g_Wcl; off=i-8192; }
  else if(i < 24576){ src=Uf; dh=g_Ufh; dl=g_Ufl; off=i-16384; }
  else if(i < 32768){ src=Up; dh=g_Uph; dl=g_Upl; off=i-24576; }
  else if(i < 57344){ src=Ui; dh=g_Uih; dl=g_Uil; off=i-32768; }
  else return;
  float2 v = *(const float2*)(src + off*2);
  uint32_t hi, lo; split_bf2(v.x, v.y, hi, lo);
  dh[off]=hi; dl[off]=lo;
}

// ----------------------------- prep: logmaps + bf16 packing -----------------------------
__global__ void k_prep(const float* __restrict__ h1, const float* __restrict__ h2,
                       const float* __restrict__ c1, const float* __restrict__ c2,
                       const float* __restrict__ x,  const float* __restrict__ h3,
                       const float* __restrict__ c3){
  int nd = (blockIdx.x*blockDim.x + threadIdx.x) >> 5;
  if(nd >= NN) return;
  int l = threadIdx.x & 31;
  int b = nd*128 + l*4;
  int bi = nd*64 + l*2;
  float v[4], w[4];
  // h1 -> l1 (fp32 + bf16), store ||h1||
  ld4(v, h1+b);
  float nr = sqrtf(wdot<4>(v,v) + 1e-15f);
  float s = __fdividef(fatanh(nr), nr);
  #pragma unroll
  for(int i=0;i<4;i++) w[i]=v[i]*s;
  st4(g_l1+b, w); pack_store(g_l1h,g_l1l,bi,w);
  if(l==0) g_nh1[nd] = nr;
  // h2 -> l2 (bf16), store ||h2||
  ld4(v, h2+b);
  nr = sqrtf(wdot<4>(v,v) + 1e-15f);
  s = __fdividef(atanf(nr), nr);
  #pragma unroll
  for(int i=0;i<4;i++) w[i]=v[i]*s;
  pack_store(g_l2h,g_l2l,bi,w);
  if(l==0) g_nh2[nd] = nr;
  // c1 -> lc1 (bf16)
  ld4(v, c1+b);
  nr = sqrtf(wdot<4>(v,v) + 1e-15f);
  s = __fdividef(fatanh(nr), nr);
  #pragma unroll
  for(int i=0;i<4;i++) w[i]=v[i]*s;
  pack_store(g_lc1h,g_lc1l,bi,w);
  // c2 -> lc2 (bf16)
  ld4(v, c2+b);
  nr = sqrtf(wdot<4>(v,v) + 1e-15f);
  s = __fdividef(atanf(nr), nr);
  #pragma unroll
  for(int i=0;i<4;i++) w[i]=v[i]*s;
  pack_store(g_lc2h,g_lc2l,bi,w);
  // raw packs
  ld4(v, x+b);  pack_store(g_xh, g_xl, bi, v);
  ld4(v, h3+b); pack_store(g_h3h,g_h3l,bi, v);
  ld4(v, c3+b); pack_store(g_c3h,g_c3l,bi, v);
}

// ----------------------------- per-node elementwise -----------------------------
__global__ void k_node(const float* __restrict__ h1, const float* __restrict__ h2,
                       const float* __restrict__ h3, const float* __restrict__ c1,
                       const float* __restrict__ c2, const float* __restrict__ c3,
                       const float* __restrict__ del_t, const float* __restrict__ dptr){
  int nd = (blockIdx.x*blockDim.x + threadIdx.x) >> 5;
  if(nd >= NN) return;
  int l = threadIdx.x & 31;
  int b = nd*128 + l*4;

  // query
  float yq[4]; ld4(yq, g_Yq+b);
  float nq = sqrtf(wdot<4>(yq,yq) + 1e-15f);
  float mp = fminf(ftanh(nq), PMF);
  float msp = ftan(nq);
  {
    float sp = __fdividef(mp,nq), ss = __fdividef(msp,nq);
    float a[4], bb[4];
    #pragma unroll
    for(int i=0;i<4;i++){ a[i]=yq[i]*sp; bb[i]=yq[i]*ss; }
    st4(g_x1p+b, a); st4(g_x1s+b, bb);
  }
  if(l==0){ g_x2p[nd]=mp*mp; g_x2s[nd]=msp*msp; }

  // gates
  float s1[4];
  {
    ld4(s1, g_Yup1+b);
    float nt = sqrtf(wdot<4>(s1,s1)+1e-15f);
    float me = fminf(ftanh(nt), PMF);
    float sc = __fdividef(me, nt);
    #pragma unroll
    for(int i=0;i<4;i++) s1[i] = fsig(s1[i]*sc);
    float ns = sqrtf(wdot<4>(s1,s1)+1e-15f);
    float sl = __fdividef(fatanh(ns), ns);
    #pragma unroll
    for(int i=0;i<4;i++) s1[i] *= sl;
  }
  float s2[4];
  {
    ld4(s2, g_Yup2+b);
    float nt = sqrtf(wdot<4>(s2,s2)+1e-15f);
    float me = ftan(nt);
    float sc = __fdividef(me, nt);
    #pragma unroll
    for(int i=0;i<4;i++) s2[i] = fsig(s2[i]*sc);
    float ns = sqrtf(wdot<4>(s2,s2)+1e-15f);
    float sl = __fdividef(atanf(ns), ns);
    #pragma unroll
    for(int i=0;i<4;i++) s2[i] *= sl;
  }
  float s3[4]; ld4(s3, g_Yup3+b);
  #pragma unroll
  for(int i=0;i<4;i++) s3[i] = fsig(s3[i]);

  float h1v[4],h2v[4],h3v[4];
  ld4(h1v, h1+b); ld4(h2v, h2+b); ld4(h3v, h3+b);
  float nh1 = g_nh1[nd], nh2 = g_nh2[nd];
  float nh3 = sqrtf(wdot<4>(h3v,h3v)+1e-15f);

  // Poincare h-branch
  float ht1p[4], ht2p[4], ht3p[4], tmp[4];
  float m1p = pwmulp_k(s1, h1v, nh1, ht1p);
  float m2p, m3p;
  {
    float mm = fminf(ftanh(atanf(nh2)), PMF);
    float sc = __fdividef(mm, nh2);
    #pragma unroll
    for(int i=0;i<4;i++) tmp[i] = h2v[i]*sc;
    m2p = pwmulp_k(s2, tmp, mm, ht2p);
  }
  {
    float mm = fminf(ftanh(nh3), PMF);
    float sc = __fdividef(mm, nh3);
    #pragma unroll
    for(int i=0;i<4;i++) tmp[i] = h3v[i]*sc;
    m3p = pwmulp_k(s3, tmp, mm, ht3p);
  }
  {
    float la = __fdividef(2.f, 1.f-m1p*m1p);
    float lb = __fdividef(2.f, 1.f-m2p*m2p);
    float lc = __fdividef(2.f, 1.f-m3p*m3p);
    float den = fmaxf(fabsf(la+lb+lc-3.f), EPSF);
    float num[4];
    #pragma unroll
    for(int i=0;i<4;i++) num[i] = la*ht1p[i]+lb*ht2p[i]+lc*ht3p[i];
    float nnum = sqrtf(wdot<4>(num,num)+1e-15f);
    float nn = __fdividef(nnum, den);
    float m = fminf(ftanh(0.5f*fatanh(nn)), PMF);
    float sc = __fdividef(3.f*m, nnum);
    #pragma unroll
    for(int i=0;i<4;i++) num[i] *= sc;
    st4(g_h1p+b, num);
    if(l==0) g_y2p[nd] = 9.f*m*m;
  }

  // Sphere h-branch
  float ht1s[4], ht2s[4], ht3s[4];
  float m2s;
  {
    float l1v[4]; ld4(l1v, g_l1+b);
    float nl1 = fatanh(nh1);
    float mm = ftan(nl1);
    float sc = __fdividef(mm, nl1);
    #pragma unroll
    for(int i=0;i<4;i++) tmp[i] = l1v[i]*sc;
    float m1s = pwmulp_k(s1, tmp, mm, ht1s);
    m2s = pwmuls_k(s2, h2v, nh2, ht2s);
    float mm3 = ftan(nh3);
    float sc3 = __fdividef(mm3, nh3);
    #pragma unroll
    for(int i=0;i<4;i++) tmp[i] = h3v[i]*sc3;
    float m3s = pwmuls_k(s3, tmp, mm3, ht3s);
    float la = __fdividef(2.f, 1.f-m1s*m1s);
    float lb = __fdividef(2.f, 1.f-m2s*m2s);
    float lc = __fdividef(2.f, 1.f-m3s*m3s);
    float den = fmaxf(fabsf(la+lb+lc-3.f), EPSF);
    float num[4];
    #pragma unroll
    for(int i=0;i<4;i++) num[i] = la*ht1s[i]+lb*ht2s[i]+lc*ht3s[i];
    float nnum = sqrtf(wdot<4>(num,num)+1e-15f);
    float nn = __fdividef(nnum, den);
    float m = fminf(ftanh(0.5f*fatanh(nn)), PMF);
    float sc2 = __fdividef(3.f*m, nnum);
    #pragma unroll
    for(int i=0;i<4;i++) num[i] *= sc2;
    st4(g_h1s+b, num);
    if(l==0) g_y2s[nd] = 9.f*m*m;
  }

  // Euclid h-branch
  {
    float e1s = __fdividef(fatanh(m1p), m1p);
    float e2s = __fdividef(atanf(m2s), m2s);
    float he[4];
    #pragma unroll
    for(int i=0;i<4;i++) he[i] = ht1p[i]*e1s + ht2s[i]*e2s + s3[i]*h3v[i];
    st4(g_h1e+b, he);
  }

  float g = __fdividef(dptr[0], del_t[nd] + 1.f);
  float nx2 = sqrtf(g*g + 1e-15f);
  float ax2 = fatanh(nx2);   // for poincare pwmulg
  float sx2 = atanf(nx2);    // for sphere pwmulg

  // ---- Poincare cell
  {
    float c1v[4]; ld4(c1v, c1+b);
    float cw[4]; ld4(cw, g_Ywc1+b);
    float nw = sqrtf(wdot<4>(cw,cw)+1e-15f);
    {
      float sc = __fdividef(fatanh(fminf(ftanh(nw),PMF)), nw);
      #pragma unroll
      for(int i=0;i<4;i++) cw[i] = ftanh(cw[i]*sc);
    }
    float nck = sqrtf(wdot<4>(cw,cw)+1e-15f);
    float mk = fminf(ftanh(nck), PMF);
    {
      float sc = __fdividef(mk, nck);
      #pragma unroll
      for(int i=0;i<4;i++) cw[i] *= sc;
    }
    // t1 = madd_p(-cskp, c1)
    float x2 = mk*mk;
    float y2 = wdot<4>(c1v,c1v);
    float xys = 0.f;
    #pragma unroll
    for(int i=0;i<4;i++) xys -= cw[i]*c1v[i];
    float xy = wred(xys);
    float cx = 1.f+2.f*xy+y2, cy = 1.f-x2;
    float idn = __fdividef(1.f, safe_den(1.f+2.f*xy+x2*y2));
    float t1[4];
    #pragma unroll
    for(int i=0;i<4;i++) t1[i] = (cx*(-cw[i]) + cy*c1v[i])*idn;
    float n2t1 = fmaxf((cx*cx*x2 + 2.f*cx*cy*xy + cy*cy*y2)*idn*idn, 0.f);
    if(n2t1 > PMF*PMF){
      float sc = PMF*rsqrtf(n2t1);
      #pragma unroll
      for(int i=0;i<4;i++) t1[i] *= sc;
      n2t1 = PMF*PMF;
    }
    // t2 = pwmulg_p(cskp, g) = cskp * (m2/mk)
    float m2 = fminf(ftanh(__fdividef(g*mk, nx2)*ax2), PMF);
    float t2s = __fdividef(m2, mk);
    // cktp = madd_p(t1, t2)
    float xys2 = 0.f;
    #pragma unroll
    for(int i=0;i<4;i++) xys2 += t1[i]*cw[i]*t2s;
    float xy2 = wred(xys2);
    x2 = n2t1; y2 = m2*m2;
    cx = 1.f+2.f*xy2+y2; cy = 1.f-x2;
    idn = __fdividef(1.f, safe_den(1.f+2.f*xy2+x2*y2));
    float ck[4];
    #pragma unroll
    for(int i=0;i<4;i++) ck[i] = (cx*t1[i] + cy*cw[i]*t2s)*idn;
    float n2ck = fmaxf((cx*cx*x2 + 2.f*cx*cy*xy2 + cy*cy*y2)*idn*idn, 0.f);
    float nckt = sqrtf(n2ck + 1e-15f);
    if(nckt > PMF){
      float sc = __fdividef(PMF, nckt);
      #pragma unroll
      for(int i=0;i<4;i++) ck[i] *= sc;
      nckt = PMF;
    }
    // f_p
    float fp[4]; ld4(fp, g_Yuf1+b);
    float nf = sqrtf(wdot<4>(fp,fp)+1e-15f);
    float scf = __fdividef(fatanh(fminf(ftanh(nf),PMF)), nf);
    #pragma unroll
    for(int i=0;i<4;i++) fp[i] = fsig(fp[i]*scf);
    float P1[4];
    float mP1 = pwmulp_k(fp, ck, nckt, P1);
    st4(g_P1+b, P1);
    if(l==0) g_lam1[nd] = __fdividef(2.f, 1.f-mP1*mP1);
  }

  // ---- Sphere cell
  {
    float c2v[4]; ld4(c2v, c2+b);
    float cw[4]; ld4(cw, g_Ywc2+b);
    float nw = sqrtf(wdot<4>(cw,cw)+1e-15f);
    {
      float sc = __fdividef(atanf(ftan(nw)), nw);
      #pragma unroll
      for(int i=0;i<4;i++) cw[i] = ftanh(cw[i]*sc);
    }
    float nck = sqrtf(wdot<4>(cw,cw)+1e-15f);
    float mk = ftan(nck);
    {
      float sc = __fdividef(mk, nck);
      #pragma unroll
      for(int i=0;i<4;i++) cw[i] *= sc;
    }
    float x2 = mk*mk;
    float y2 = wdot<4>(c2v,c2v);
    float xys = 0.f;
    #pragma unroll
    for(int i=0;i<4;i++) xys -= cw[i]*c2v[i];
    float xy = wred(xys);
    float cx = 1.f-2.f*xy-y2, cy = 1.f+x2;
    float idn = __fdividef(1.f, safe_den(1.f-2.f*xy+x2*y2));
    float t1[4];
    #pragma unroll
    for(int i=0;i<4;i++) t1[i] = (cx*(-cw[i]) + cy*c2v[i])*idn;
    float n2t1 = fmaxf((cx*cx*x2 + 2.f*cx*cy*xy + cy*cy*y2)*idn*idn, 0.f);
    float m2 = ftan(__fdividef(g*mk, nx2)*sx2);
    float t2s = __fdividef(m2, mk);
    float xys2 = 0.f;
    #pragma unroll
    for(int i=0;i<4;i++) xys2 += t1[i]*cw[i]*t2s;
    float xy2 = wred(xys2);
    x2 = n2t1; y2 = m2*m2;
    cx = 1.f-2.f*xy2-y2; cy = 1.f+x2;
    idn = __fdividef(1.f, safe_den(1.f-2.f*xy2+x2*y2));
    float ck[4];
    #pragma unroll
    for(int i=0;i<4;i++) ck[i] = (cx*t1[i] + cy*cw[i]*t2s)*idn;
    float n2ck = fmaxf((cx*cx*x2 + 2.f*cx*cy*xy2 + cy*cy*y2)*idn*idn, 0.f);
    float nckt = sqrtf(n2ck + 1e-15f);
    float fs[4]; ld4(fs, g_Yuf2+b);
    float nf = sqrtf(wdot<4>(fs,fs)+1e-15f);
    float scf = __fdividef(atanf(ftan(nf)), nf);
    #pragma unroll
    for(int i=0;i<4;i++) fs[i] = fsig(fs[i]*scf);
    float P2[4];
    float mP2 = pwmuls_k(fs, ck, nckt, P2);
    st4(g_P2+b, P2);
    if(l==0) g_lam2[nd] = __fdividef(2.f, 1.f+mP2*mP2);
  }

  // ---- Euclid cell
  {
    float c3v[4]; ld4(c3v, c3+b);
    float cske[4]; ld4(cske, g_Ywc3+b);
    float fe[4]; ld4(fe, g_Yuf3+b);
    float E3[4];
    #pragma unroll
    for(int i=0;i<4;i++){
      float ck = ftanh(cske[i]);
      E3[i] = fsig(fe[i])*(c3v[i] - ck + ck*g);
    }
    st4(g_E3+b, E3);
  }
}

// ----------------------------- gather + attention + cell reductions -----------------------------
__global__ void k_attn(const int* __restrict__ nbr){
  int nd = (blockIdx.x*blockDim.x + threadIdx.x) >> 5;
  if(nd >= NN) return;
  int l = threadIdx.x & 31;
  int b = nd*128 + l*4;
  int bi = nd*64 + l*2;
  const int* nb = nbr + nd*8;
  int j8[8], nj[8];
  #pragma unroll
  for(int k=0;k<8;k++){ j8[k] = nb[k]; nj[k] = j8[k]*128 + l*4; }

  float hk[8][4], sc[8], y2[8];

  // ---- Poincare attention
  {
    float xq[4]; ld4(xq, g_x1p+b);
    float x2 = g_x2p[nd];
    #pragma unroll
    for(int k=0;k<8;k++){
      ld4(hk[k], g_h1p + nj[k]);
      y2[k] = g_y2p[j8[k]];
      float s = 0.f;
      #pragma unroll
      for(int i=0;i<4;i++) s -= xq[i]*hk[k][i];
      float xy = wred(s);
      float cx = 1.f + 2.f*xy + y2[k];
      float cy = 1.f - x2;
      float dn = safe_den(1.f + 2.f*xy + x2*y2[k]);
      float o2 = cx*cx*x2 + 2.f*cx*cy*xy + cy*cy*y2[k];
      float nr = fminf(__fdividef(sqrtf(fmaxf(o2,0.f) + 1e-15f), fabsf(dn)), PMF);
      sc[k] = -2.f*fatanh(nr);
    }
    softmax8(sc);
    float num[4] = {0,0,0,0};
    float ds = 0.f;
    #pragma unroll
    for(int k=0;k<8;k++){
      float lam = __fdividef(2.f, 1.f - y2[k]);
      float wk = sc[k]*lam;
      #pragma unroll
      for(int i=0;i<4;i++) num[i] += wk*hk[k][i];
      ds += sc[k]*(lam - 1.f);
    }
    float den = fmaxf(fabsf(ds), EPSF);
    float nnum = sqrtf(wdot<4>(num,num) + 1e-15f);
    float nn = __fdividef(nnum, den);
    float m = fminf(ftanh(0.5f*fatanh(nn)), PMF);
    float st = __fdividef(fatanh(m), nnum);
    #pragma unroll
    for(int i=0;i<4;i++) num[i] *= st;
    pack_store(g_A1h, g_A1l, bi, num);
  }

  // ---- Sphere attention
  {
    float xq[4]; ld4(xq, g_x1s+b);
    float x2 = g_x2s[nd];
    #pragma unroll
    for(int k=0;k<8;k++){
      ld4(hk[k], g_h1s + nj[k]);
      y2[k] = g_y2s[j8[k]];
      float s = 0.f;
      #pragma unroll
      for(int i=0;i<4;i++) s -= xq[i]*hk[k][i];
      float xy = wred(s);
      float cx = 1.f - 2.f*xy - y2[k];
      float cy = 1.f + x2;
      float dn = safe_den(1.f - 2.f*xy + x2*y2[k]);
      float o2 = cx*cx*x2 + 2.f*cx*cy*xy + cy*cy*y2[k];
      float nr = __fdividef(sqrtf(fmaxf(o2,0.f) + 1e-15f), fabsf(dn));
      sc[k] = -2.f*atanf(nr);
    }
    softmax8(sc);
    float num[4] = {0,0,0,0};
    float ds = 0.f;
    #pragma unroll
    for(int k=0;k<8;k++){
      float lam = __fdividef(2.f, 1.f + y2[k]);
      float wk = sc[k]*lam;
      #pragma unroll
      for(int i=0;i<4;i++) num[i] += wk*hk[k][i];
      ds += sc[k]*(lam - 1.f);
    }
    float den = fmaxf(fabsf(ds), EPSF);
    float nnum = sqrtf(wdot<4>(num,num) + 1e-15f);
    float nn = __fdividef(nnum, den);
    float m = ftan(0.5f*atanf(nn));
    float st = __fdividef(atanf(m), nnum);
    #pragma unroll
    for(int i=0;i<4;i++) num[i] *= st;
    pack_store(g_A2h, g_A2l, bi, num);
  }

  // ---- Euclid attention
  {
    float xq[4]; ld4(xq, g_Yq+b);
    const float isq = 0.08838834764831845f;
    #pragma unroll
    for(int k=0;k<8;k++){
      ld4(hk[k], g_h1e + nj[k]);
      sc[k] = wdot<4>(hk[k], xq) * isq;
    }
    softmax8(sc);
    float num[4] = {0,0,0,0};
    #pragma unroll
    for(int k=0;k<8;k++){
      #pragma unroll
      for(int i=0;i<4;i++) num[i] += sc[k]*hk[k][i];
    }
    pack_store(g_A3h, g_A3l, bi, num);
  }

  // ---- Poincare cell reduction
  {
    float num[4] = {0,0,0,0};
    float ds = 0.f;
    #pragma unroll
    for(int k=0;k<8;k++){
      float pv[4]; ld4(pv, g_P1 + nj[k]);
      float lam = g_lam1[j8[k]];
      #pragma unroll
      for(int i=0;i<4;i++) num[i] += lam*pv[i];
      ds += lam - 1.f;
    }
    float den = fmaxf(fabsf(ds), EPSF);
    float nnum = sqrtf(wdot<4>(num,num) + 1e-15f);
    float nn = __fdividef(nnum, den);
    float m = fminf(ftanh(0.5f*fatanh(nn)), PMF);
    float st = __fdividef(m, nnum);
    #pragma unroll
    for(int i=0;i<4;i++) num[i] *= st;
    st4(g_c1o+b, num);
    if(l==0) g_n2c1o[nd] = m*m;
  }
  // ---- Sphere cell reduction
  {
    float num[4] = {0,0,0,0};
    float ds = 0.f;
    #pragma unroll
    for(int k=0;k<8;k++){
      float pv[4]; ld4(pv, g_P2 + nj[k]);
      float lam = g_lam2[j8[k]];
      #pragma unroll
      for(int i=0;i<4;i++) num[i] += lam*pv[i];
      ds += lam - 1.f;
    }
    float den = fmaxf(fabsf(ds), EPSF);
    float nnum = sqrtf(wdot<4>(num,num) + 1e-15f);
    float nn = __fdividef(nnum, den);
    float m = ftan(0.5f*atanf(nn));
    float st = __fdividef(m, nnum);
    #pragma unroll
    for(int i=0;i<4;i++) num[i] *= st;
    st4(g_c2o+b, num);
    if(l==0) g_n2c2o[nd] = m*m;
  }
  // ---- Euclid cell sum
  {
    float acc[4] = {0,0,0,0};
    #pragma unroll
    for(int k=0;k<8;k++){
      float ev[4]; ld4(ev, g_E3 + nj[k]);
      #pragma unroll
      for(int i=0;i<4;i++) acc[i] += ev[i];
    }
    st4(g_c3o+b, acc);
  }
}

// ----------------------------- final epilogue -----------------------------
__global__ void k_final(const float* __restrict__ iou1, const float* __restrict__ iou2,
                        const float* __restrict__ iou3, float* __restrict__ out){
  int nd = (blockIdx.x*blockDim.x + threadIdx.x) >> 5;
  if(nd >= NN) return;
  int l = threadIdx.x & 31;
  int b = nd*128 + l*4;
  int b3 = nd*384 + l*4;

  // ---- Poincare
  {
    float z[12], io[12];
    #pragma unroll
    for(int c=0;c<3;c++){ ld4(z+4*c, g_Z1 + b3 + 128*c); ld4(io+4*c, iou1 + b3 + 128*c); }
    float nz = sqrtf(wdot<12>(z,z)+1e-15f);
    float mz = fminf(ftanh(nz), PMF);
    {
      float sc = __fdividef(mz, nz);
      #pragma unroll
      for(int i=0;i<12;i++) z[i] *= sc;
    }
    float x2 = wdot<12>(io,io);
    float xy = wdot<12>(io,z);
    float y2 = mz*mz;
    float cx = 1.f+2.f*xy+y2, cy = 1.f-x2;
    float idn = __fdividef(1.f, safe_den(1.f+2.f*xy+x2*y2));
    float ni[12];
    #pragma unroll
    for(int i=0;i<12;i++) ni[i] = (cx*io[i] + cy*z[i])*idn;
    float n2ni = fmaxf((cx*cx*x2 + 2.f*cx*cy*xy + cy*cy*y2)*idn*idn, 0.f);
    if(n2ni > PMF*PMF){
      float sc = PMF*rsqrtf(n2ni);
      #pragma unroll
      for(int i=0;i<12;i++) ni[i] *= sc;
    }
    float ip[4], op[4], up[4];
    {
      float n0 = sqrtf(wdot<4>(ni,ni)+1e-15f);
      float s0 = __fdividef(fatanh(n0), n0);
      float n1 = sqrtf(wdot<4>(ni+4,ni+4)+1e-15f);
      float s1 = __fdividef(fatanh(n1), n1);
      float n2 = sqrtf(wdot<4>(ni+8,ni+8)+1e-15f);
      float s2 = __fdividef(fatanh(n2), n2);
      #pragma unroll
      for(int i=0;i<4;i++){
        ip[i] = fsig(ni[i]*s0);
        op[i] = fsig(ni[4+i]*s1);
        up[i] = ftanh(ni[8+i]*s2);
      }
    }
    float nup = sqrtf(wdot<4>(up,up)+1e-15f);
    float t[4];
    float mt = pwmulp_k(ip, up, nup, t);
    float cc[4]; ld4(cc, g_c1o+b);
    float y2c = g_n2c1o[nd];
    float xys = 0.f;
    #pragma unroll
    for(int i=0;i<4;i++) xys += t[i]*cc[i];
    float xyc = wred(xys);
    float x2c = mt*mt;
    float cxc = 1.f+2.f*xyc+y2c, cyc = 1.f-x2c;
    float idnc = __fdividef(1.f, safe_den(1.f+2.f*xyc+x2c*y2c));
    float nc[4];
    #pragma unroll
    for(int i=0;i<4;i++) nc[i] = (cxc*t[i] + cyc*cc[i])*idnc;
    float n2nc = fmaxf((cxc*cxc*x2c + 2.f*cxc*cyc*xyc + cyc*cyc*y2c)*idnc*idnc, 0.f);
    float nnc = sqrtf(n2nc + 1e-15f);
    if(nnc > PMF){
      float sc = __fdividef(PMF, nnc);
      #pragma unroll
      for(int i=0;i<4;i++) nc[i] *= sc;
      nnc = PMF;
    }
    float lt[4];
    {
      float sc = __fdividef(fatanh(nnc), nnc);
      #pragma unroll
      for(int i=0;i<4;i++) lt[i] = ftanh(nc[i]*sc);
    }
    float nlt = sqrtf(wdot<4>(lt,lt)+1e-15f);
    float nh[4];
    pwmulp_k(op, lt, nlt, nh);
    st4(out + 0*NN*128 + b, nh);
    st4(out + 1*NN*128 + b, nc);
  }

  // ---- Sphere
  {
    float z[12], io[12];
    #pragma unroll
    for(int c=0;c<3;c++){ ld4(z+4*c, g_Z2 + b3 + 128*c); ld4(io+4*c, iou2 + b3 + 128*c); }
    float nz = sqrtf(wdot<12>(z,z)+1e-15f);
    float mz = ftan(nz);
    {
      float sc = __fdividef(mz, nz);
      #pragma unroll
      for(int i=0;i<12;i++) z[i] *= sc;
    }
    float x2 = wdot<12>(io,io);
    float xy = wdot<12>(io,z);
    float y2 = mz*mz;
    float cx = 1.f-2.f*xy-y2, cy = 1.f+x2;
    float idn = __fdividef(1.f, safe_den(1.f-2.f*xy+x2*y2));
    float ni[12];
    #pragma unroll
    for(int i=0;i<12;i++) ni[i] = (cx*io[i] + cy*z[i])*idn;
    float ip[4], op[4], up[4];
    {
      float n0 = sqrtf(wdot<4>(ni,ni)+1e-15f);
      float s0 = __fdividef(atanf(n0), n0);
      float n1 = sqrtf(wdot<4>(ni+4,ni+4)+1e-15f);
      float s1 = __fdividef(atanf(n1), n1);
      float n2 = sqrtf(wdot<4>(ni+8,ni+8)+1e-15f);
      float s2 = __fdividef(atanf(n2), n2);
      #pragma unroll
      for(int i=0;i<4;i++){
        ip[i] = fsig(ni[i]*s0);
        op[i] = fsig(ni[4+i]*s1);
        up[i] = ftanh(ni[8+i]*s2);
      }
    }
    float nup = sqrtf(wdot<4>(up,up)+1e-15f);
    float t[4];
    float mt = pwmuls_k(ip, up, nup, t);
    float cc[4]; ld4(cc, g_c2o+b);
    float y2c = g_n2c2o[nd];
    float xys = 0.f;
    #pragma unroll
    for(int i=0;i<4;i++) xys += t[i]*cc[i];
    float xyc = wred(xys);
    float x2c = mt*mt;
    float cxc = 1.f-2.f*xyc-y2c, cyc = 1.f+x2c;
    float idnc = __fdividef(1.f, safe_den(1.f-2.f*xyc+x2c*y2c));
    float nc[4];
    #pragma unroll
    for(int i=0;i<4;i++) nc[i] = (cxc*t[i] + cyc*cc[i])*idnc;
    float n2nc = fmaxf((cxc*cxc*x2c + 2.f*cxc*cyc*xyc + cyc*cyc*y2c)*idnc*idnc, 0.f);
    float nnc = sqrtf(n2nc + 1e-15f);
    float lt[4];
    {
      float sc = __fdividef(atanf(nnc), nnc);
      #pragma unroll
      for(int i=0;i<4;i++) lt[i] = ftanh(nc[i]*sc);
    }
    float nlt = sqrtf(wdot<4>(lt,lt)+1e-15f);
    float nh[4];
    pwmuls_k(op, lt, nlt, nh);
    st4(out + 2*NN*128 + b, nh);
    st4(out + 3*NN*128 + b, nc);
  }

  // ---- Euclid
  {
    float z[12], io[12];
    #pragma unroll
    for(int c=0;c<3;c++){ ld4(z+4*c, g_Z3 + b3 + 128*c); ld4(io+4*c, iou3 + b3 + 128*c); }
    float cc[4]; ld4(cc, g_c3o+b);
    float nc[4], nh[4];
    #pragma unroll
    for(int i=0;i<4;i++){
      float ip = fsig(io[i]   + z[i]);
      float op = fsig(io[4+i] + z[4+i]);
      float up = ftanh(io[8+i] + z[8+i]);
      nc[i] = ip*up + cc[i];
      nh[i] = op*ftanh(nc[i]);
    }
    st4(out + 4*NN*128 + b, nh);
    st4(out + 5*NN*128 + b, nc);
  }
}

// ----------------------------- launch -----------------------------
extern "C" void kernel_launch(void* const* d_in, const int* in_sizes, int n_in,
                              void* d_out, int out_size){
  const float* x     = (const float*)d_in[0];
  const float* h1    = (const float*)d_in[1];
  const float* c1    = (const float*)d_in[2];
  const float* h2    = (const float*)d_in[3];
  const float* c2    = (const float*)d_in[4];
  const float* h3    = (const float*)d_in[5];
  const float* c3    = (const float*)d_in[6];
  const float* del_t = (const float*)d_in[7];
  const float* iou1  = (const float*)d_in[8];
  const float* iou2  = (const float*)d_in[9];
  const float* iou3  = (const float*)d_in[10];
  const float* Wq_w  = (const float*)d_in[11];
  const float* Wq_b  = (const float*)d_in[12];
  const float* Wc_w  = (const float*)d_in[13];
  const float* Wc_b  = (const float*)d_in[14];
  const float* Uf_w  = (const float*)d_in[15];
  const float* Uf_b  = (const float*)d_in[16];
  const float* Up_w  = (const float*)d_in[17];
  const float* Up_b  = (const float*)d_in[18];
  const float* Uiou_w= (const float*)d_in[19];
  const float* Uiou_b= (const float*)d_in[20];
  const float* dptr  = (const float*)d_in[21];
  const int*   nbr   = (const int*)d_in[22];
  float* out = (float*)d_out;

  cudaFuncSetAttribute(k_gemm1, cudaFuncAttributeMaxDynamicSharedMemorySize, GSMEM);
  cudaFuncSetAttribute(k_gemm2, cudaFuncAttributeMaxDynamicSharedMemorySize, GSMEM);

  k_cvtw<<<224, 256>>>(Wq_w, Wc_w, Uf_w, Up_w, Uiou_w);
  k_prep<<<NN/8, 256>>>(h1, h2, c1, c2, x, h3, c3);
  k_gemm1<<<dim3(NN/64, 1, 10), 256, GSMEM>>>(Wq_b, Wc_b, Uf_b, Up_b);
  k_node<<<NN/8, 256>>>(h1, h2, h3, c1, c2, c3, del_t, dptr);
  k_attn<<<NN/8, 256>>>(nbr);
  k_gemm2<<<dim3(NN/64, 3, 3), 256, GSMEM>>>(Uiou_b);
  k_final<<<NN/8, 256>>>(iou1, iou2, iou3, out);
}

// round 7
// speedup vs baseline: 2.0669x; 1.0459x over previous
#include <cuda_runtime.h>
#include <cuda_bf16.h>
#include <math.h>
#include <stdint.h>

#define NN 8192
#define HH 128
#define H3 384
#define EPSF 1e-6f
#define PMF 0.9999f
#define PADU 68
#define GSMEM (384 * PADU * 4)

// ----------------------------- fp32 scratch -----------------------------
__device__ float g_Yq[NN*HH];
__device__ float g_Yup1[NN*HH], g_Yup2[NN*HH], g_Yup3[NN*HH];
__device__ float g_Yuf1[NN*HH], g_Yuf2[NN*HH], g_Yuf3[NN*HH];
__device__ float g_Ywc1[NN*HH], g_Ywc2[NN*HH], g_Ywc3[NN*HH];
__device__ float g_h1p[NN*HH], g_h1s[NN*HH], g_h1e[NN*HH];
__device__ float g_P1[NN*HH], g_P2[NN*HH], g_E3[NN*HH];
__device__ float g_c1o[NN*HH], g_c2o[NN*HH], g_c3o[NN*HH];
__device__ float g_Z1[NN*H3], g_Z2[NN*H3], g_Z3[NN*H3];
// per-node scalars
__device__ float g_y2p[NN], g_y2s[NN], g_lam1[NN], g_lam2[NN];
__device__ float g_nh1[NN], g_nh2[NN];
__device__ float g_n2c1o[NN], g_n2c2o[NN];
// bf16 hi/lo packed (uint32 = bf16x2)
__device__ uint32_t g_xh[NN*64],  g_xl[NN*64];
__device__ uint32_t g_l1h[NN*64], g_l1l[NN*64];
__device__ uint32_t g_l2h[NN*64], g_l2l[NN*64];
__device__ uint32_t g_h3h[NN*64], g_h3l[NN*64];
__device__ uint32_t g_lc1h[NN*64], g_lc1l[NN*64];
__device__ uint32_t g_lc2h[NN*64], g_lc2l[NN*64];
__device__ uint32_t g_c3h[NN*64], g_c3l[NN*64];
__device__ uint32_t g_A1h[NN*64], g_A1l[NN*64];
__device__ uint32_t g_A2h[NN*64], g_A2l[NN*64];
__device__ uint32_t g_A3h[NN*64], g_A3l[NN*64];
__device__ uint32_t g_Wqh[128*64], g_Wql[128*64];
__device__ uint32_t g_Wch[128*64], g_Wcl[128*64];
__device__ uint32_t g_Ufh[128*64], g_Ufl[128*64];
__device__ uint32_t g_Uph[128*64], g_Upl[128*64];
__device__ uint32_t g_Uih[384*64], g_Uil[384*64];

// ----------------------------- fast math -----------------------------
__device__ __forceinline__ float ftanh(float x){
  float a = fabsf(x);
  float r;
  if(a < 0.105f){
    float a2 = a*a;
    r = a*(1.f - a2*(0.33333334f - a2*0.13333334f));
  } else {
    float t = __expf(-2.f*a);
    r = __fdividef(1.f - t, 1.f + t);
  }
  return copysignf(r, x);
}
__device__ __forceinline__ float fatanh(float u){
  u = fminf(fmaxf(u, -1.f + 1e-5f), 1.f - 1e-5f);
  float a = fabsf(u);
  float r;
  if(a < 0.105f){
    float a2 = a*a;
    r = a*(1.f + a2*(0.33333334f + a2*0.2f));
  } else {
    r = 0.5f*__logf(__fdividef(1.f + a, 1.f - a));
  }
  return copysignf(r, u);
}
__device__ __forceinline__ float fsig(float x){
  return __fdividef(1.f, 1.f + __expf(-x));
}
__device__ __forceinline__ float ftan(float u){
  u = fminf(fmaxf(u, -1.47079f), 1.47079f);
  return __tanf(u);
}
__device__ __forceinline__ float safe_den(float d){
  return d >= 0.f ? fmaxf(d, EPSF) : fminf(d, -EPSF);
}

// ----------------------------- warp helpers -----------------------------
__device__ __forceinline__ float wred(float s){
  #pragma unroll
  for(int o=16;o;o>>=1) s += __shfl_xor_sync(0xffffffffu, s, o);
  return s;
}
template<int R> __device__ __forceinline__ float wdot(const float* a, const float* b){
  float s=0.f;
  #pragma unroll
  for(int i=0;i<R;i++) s += a[i]*b[i];
  return wred(s);
}
__device__ __forceinline__ void ld4(float* v, const float* p){
  float4 t = *(const float4*)p; v[0]=t.x; v[1]=t.y; v[2]=t.z; v[3]=t.w;
}
__device__ __forceinline__ void st4(float* p, const float* v){
  *(float4*)p = make_float4(v[0],v[1],v[2],v[3]);
}

// pwmul with known ||x||, Poincare — returns result norm
__device__ __forceinline__ float pwmulp_k(const float* w, const float* x, float nx, float* o){
  float wx[4];
  #pragma unroll
  for(int i=0;i<4;i++) wx[i] = w[i]*x[i];
  float nwx = sqrtf(wdot<4>(wx,wx) + 1e-15f);
  float m = fminf(ftanh(__fdividef(nwx,nx)*fatanh(nx)), PMF);
  float s = __fdividef(m, nwx);
  #pragma unroll
  for(int i=0;i<4;i++) o[i] = wx[i]*s;
  return m;
}
// pwmul with known ||x||, sphere — returns result norm
__device__ __forceinline__ float pwmuls_k(const float* w, const float* x, float nx, float* o){
  float wx[4];
  #pragma unroll
  for(int i=0;i<4;i++) wx[i] = w[i]*x[i];
  float nwx = sqrtf(wdot<4>(wx,wx) + 1e-15f);
  float m = ftan(__fdividef(nwx,nx)*atanf(nx));
  float s = __fdividef(m, nwx);
  #pragma unroll
  for(int i=0;i<4;i++) o[i] = wx[i]*s;
  return m;
}
__device__ __forceinline__ void softmax8(float* s){
  float m = s[0];
  #pragma unroll
  for(int k=1;k<8;k++) m = fmaxf(m, s[k]);
  float sum = 0.f;
  #pragma unroll
  for(int k=0;k<8;k++){ s[k] = __expf(s[k]-m); sum += s[k]; }
  float inv = __fdividef(1.f, sum);
  #pragma unroll
  for(int k=0;k<8;k++) s[k] *= inv;
}

// ----------------------------- bf16 packing -----------------------------
__device__ __forceinline__ uint32_t pack_bf2(float f0, float f1){
  __nv_bfloat16 b0 = __float2bfloat16_rn(f0);
  __nv_bfloat16 b1 = __float2bfloat16_rn(f1);
  return ((uint32_t)__bfloat16_as_ushort(b1)<<16) | (uint32_t)__bfloat16_as_ushort(b0);
}
__device__ __forceinline__ void split_bf2(float f0, float f1, uint32_t& hi, uint32_t& lo){
  __nv_bfloat16 b0 = __float2bfloat16_rn(f0);
  __nv_bfloat16 b1 = __float2bfloat16_rn(f1);
  hi = ((uint32_t)__bfloat16_as_ushort(b1)<<16) | (uint32_t)__bfloat16_as_ushort(b0);
  lo = pack_bf2(f0 - __bfloat162float(b0), f1 - __bfloat162float(b1));
}
__device__ __forceinline__ void pack_store(uint32_t* dh, uint32_t* dl, int idx, const float* v){
  uint32_t h0,l0,h1,l1;
  split_bf2(v[0],v[1],h0,l0);
  split_bf2(v[2],v[3],h1,l1);
  *(uint2*)(dh+idx) = make_uint2(h0,h1);
  *(uint2*)(dl+idx) = make_uint2(l0,l1);
}

// ----------------------------- GEMM (pre-packed bf16 3-term) -----------------------------
__device__ __forceinline__ void mma16(float* d, const uint32_t* a, const uint32_t* b){
  asm volatile("mma.sync.aligned.m16n8k16.row.col.f32.bf16.bf16.f32 "
    "{%0,%1,%2,%3},{%4,%5,%6,%7},{%8,%9},{%0,%1,%2,%3};"
    : "+f"(d[0]),"+f"(d[1]),"+f"(d[2]),"+f"(d[3])
    : "r"(a[0]),"r"(a[1]),"r"(a[2]),"r"(a[3]),"r"(b[0]),"r"(b[1]));
}

__device__ __forceinline__ void gemm_pk(const uint32_t* __restrict__ AhG, const uint32_t* __restrict__ AlG,
                                        const uint32_t* __restrict__ BhG, const uint32_t* __restrict__ BlG,
                                        const float* __restrict__ bias, float* __restrict__ C, int HO){
  extern __shared__ uint32_t sh[];
  uint32_t* Ah = sh;
  uint32_t* Al = sh + 64*PADU;
  uint32_t* Bh = sh + 128*PADU;
  uint32_t* Bl = sh + 256*PADU;
  const int m0 = blockIdx.x*64;
  const int n0 = blockIdx.y*128;
  const int t = threadIdx.x;
  const int lane = t & 31, w = t >> 5;
  const int wm = w >> 2, wn = w & 3;
  const int gid = lane >> 2, tig = lane & 3;

  #pragma unroll
  for(int i=0;i<4;i++){
    int p = t + i*256; int r = p>>4, c = (p&15)*4;
    *(uint4*)(Ah + r*PADU + c) = *(const uint4*)(AhG + (m0+r)*64 + c);
    *(uint4*)(Al + r*PADU + c) = *(const uint4*)(AlG + (m0+r)*64 + c);
  }
  #pragma unroll
  for(int i=0;i<8;i++){
    int p = t + i*256; int r = p>>4, c = (p&15)*4;
    *(uint4*)(Bh + r*PADU + c) = *(const uint4*)(BhG + (n0+r)*64 + c);
    *(uint4*)(Bl + r*PADU + c) = *(const uint4*)(BlG + (n0+r)*64 + c);
  }
  __syncthreads();

  float acc[2][4][4];
  #pragma unroll
  for(int mt=0;mt<2;mt++)
    #pragma unroll
    for(int nt=0;nt<4;nt++)
      #pragma unroll
      for(int i=0;i<4;i++) acc[mt][nt][i]=0.f;

  #pragma unroll
  for(int s=0;s<8;s++){
    int k2 = s*8;
    uint32_t ah[2][4], al[2][4];
    #pragma unroll
    for(int mt=0;mt<2;mt++){
      int r = wm*32 + mt*16 + gid;
      ah[mt][0]=Ah[r*PADU+k2+tig];       al[mt][0]=Al[r*PADU+k2+tig];
      ah[mt][1]=Ah[(r+8)*PADU+k2+tig];   al[mt][1]=Al[(r+8)*PADU+k2+tig];
      ah[mt][2]=Ah[r*PADU+k2+tig+4];     al[mt][2]=Al[r*PADU+k2+tig+4];
      ah[mt][3]=Ah[(r+8)*PADU+k2+tig+4]; al[mt][3]=Al[(r+8)*PADU+k2+tig+4];
    }
    uint32_t bh[4][2], bl[4][2];
    #pragma unroll
    for(int nt=0;nt<4;nt++){
      int nr = wn*32 + nt*8 + gid;
      bh[nt][0]=Bh[nr*PADU+k2+tig];   bl[nt][0]=Bl[nr*PADU+k2+tig];
      bh[nt][1]=Bh[nr*PADU+k2+tig+4]; bl[nt][1]=Bl[nr*PADU+k2+tig+4];
    }
    #pragma unroll
    for(int mt=0;mt<2;mt++)
      #pragma unroll
      for(int nt=0;nt<4;nt++){
        mma16(acc[mt][nt], al[mt], bh[nt]);
        mma16(acc[mt][nt], ah[mt], bl[nt]);
        mma16(acc[mt][nt], ah[mt], bh[nt]);
      }
  }

  #pragma unroll
  for(int mt=0;mt<2;mt++){
    int r = m0 + wm*32 + mt*16 + gid;
    #pragma unroll
    for(int nt=0;nt<4;nt++){
      int c = n0 + wn*32 + nt*8 + tig*2;
      float b0 = bias[c], b1 = bias[c+1];
      *(float2*)(C + r*HO + c)     = make_float2(acc[mt][nt][0]+b0, acc[mt][nt][1]+b1);
      *(float2*)(C + (r+8)*HO + c) = make_float2(acc[mt][nt][2]+b0, acc[mt][nt][3]+b1);
    }
  }
}

__global__ void __launch_bounds__(256) k_gemm1(const float* __restrict__ bq, const float* __restrict__ bc,
                                               const float* __restrict__ bf, const float* __restrict__ bp){
  const uint32_t *Ah,*Al,*Bh,*Bl; const float* B; float* C;
  switch(blockIdx.z){
    case 0: Ah=g_xh;  Al=g_xl;  Bh=g_Wqh; Bl=g_Wql; B=bq; C=g_Yq;   break;
    case 1: Ah=g_l1h; Al=g_l1l; Bh=g_Uph; Bl=g_Upl; B=bp; C=g_Yup1; break;
    case 2: Ah=g_l2h; Al=g_l2l; Bh=g_Uph; Bl=g_Upl; B=bp; C=g_Yup2; break;
    case 3: Ah=g_h3h; Al=g_h3l; Bh=g_Uph; Bl=g_Upl; B=bp; C=g_Yup3; break;
    case 4: Ah=g_l1h; Al=g_l1l; Bh=g_Ufh; Bl=g_Ufl; B=bf; C=g_Yuf1; break;
    case 5: Ah=g_l2h; Al=g_l2l; Bh=g_Ufh; Bl=g_Ufl; B=bf; C=g_Yuf2; break;
    case 6: Ah=g_h3h; Al=g_h3l; Bh=g_Ufh; Bl=g_Ufl; B=bf; C=g_Yuf3; break;
    case 7: Ah=g_lc1h;Al=g_lc1l;Bh=g_Wch; Bl=g_Wcl; B=bc; C=g_Ywc1; break;
    case 8: Ah=g_lc2h;Al=g_lc2l;Bh=g_Wch; Bl=g_Wcl; B=bc; C=g_Ywc2; break;
    default:Ah=g_c3h; Al=g_c3l; Bh=g_Wch; Bl=g_Wcl; B=bc; C=g_Ywc3; break;
  }
  gemm_pk(Ah, Al, Bh, Bl, B, C, 128);
}

__global__ void __launch_bounds__(256) k_gemm2(const float* __restrict__ bi){
  const uint32_t *Ah,*Al; float* C;
  switch(blockIdx.z){
    case 0: Ah=g_A1h; Al=g_A1l; C=g_Z1; break;
    case 1: Ah=g_A2h; Al=g_A2l; C=g_Z2; break;
    default:Ah=g_A3h; Al=g_A3l; C=g_Z3; break;
  }
  gemm_pk(Ah, Al, g_Uih, g_Uil, bi, C, 384);
}

// ----------------------------- prep: logmaps + bf16 packing + weight cvt -----------------------------
__global__ void k_prep(const float* __restrict__ h1, const float* __restrict__ h2,
                       const float* __restrict__ c1, const float* __restrict__ c2,
                       const float* __restrict__ x,  const float* __restrict__ h3,
                       const float* __restrict__ c3,
                       const float* __restrict__ Wq, const float* __restrict__ Wc,
                       const float* __restrict__ Uf, const float* __restrict__ Up,
                       const float* __restrict__ Ui){
  if(blockIdx.x >= NN/8){
    // weight conversion blocks
    int i = (blockIdx.x - NN/8)*256 + threadIdx.x;
    const float* src; uint32_t *dh, *dl; int off;
    if(i < 8192){ src=Wq; dh=g_Wqh; dl=g_Wql; off=i; }
    else if(i < 16384){ src=Wc; dh=g_Wch; dl=g_Wcl; off=i-8192; }
    else if(i < 24576){ src=Uf; dh=g_Ufh; dl=g_Ufl; off=i-16384; }
    else if(i < 32768){ src=Up; dh=g_Uph; dl=g_Upl; off=i-24576; }
    else if(i < 57344){ src=Ui; dh=g_Uih; dl=g_Uil; off=i-32768; }
    else return;
    float2 v = *(const float2*)(src + off*2);
    uint32_t hi, lo; split_bf2(v.x, v.y, hi, lo);
    dh[off]=hi; dl[off]=lo;
    return;
  }
  int nd = (blockIdx.x*blockDim.x + threadIdx.x) >> 5;
  int l = threadIdx.x & 31;
  int b = nd*128 + l*4;
  int bi = nd*64 + l*2;
  float v[4], w[4];
  // h1 -> l1 (bf16), store ||h1||
  ld4(v, h1+b);
  float nr = sqrtf(wdot<4>(v,v) + 1e-15f);
  float s = __fdividef(fatanh(nr), nr);
  #pragma unroll
  for(int i=0;i<4;i++) w[i]=v[i]*s;
  pack_store(g_l1h,g_l1l,bi,w);
  if(l==0) g_nh1[nd] = nr;
  // h2 -> l2 (bf16), store ||h2||
  ld4(v, h2+b);
  nr = sqrtf(wdot<4>(v,v) + 1e-15f);
  s = __fdividef(atanf(nr), nr);
  #pragma unroll
  for(int i=0;i<4;i++) w[i]=v[i]*s;
  pack_store(g_l2h,g_l2l,bi,w);
  if(l==0) g_nh2[nd] = nr;
  // c1 -> lc1 (bf16)
  ld4(v, c1+b);
  nr = sqrtf(wdot<4>(v,v) + 1e-15f);
  s = __fdividef(fatanh(nr), nr);
  #pragma unroll
  for(int i=0;i<4;i++) w[i]=v[i]*s;
  pack_store(g_lc1h,g_lc1l,bi,w);
  // c2 -> lc2 (bf16)
  ld4(v, c2+b);
  nr = sqrtf(wdot<4>(v,v) + 1e-15f);
  s = __fdividef(atanf(nr), nr);
  #pragma unroll
  for(int i=0;i<4;i++) w[i]=v[i]*s;
  pack_store(g_lc2h,g_lc2l,bi,w);
  // raw packs
  ld4(v, x+b);  pack_store(g_xh, g_xl, bi, v);
  ld4(v, h3+b); pack_store(g_h3h,g_h3l,bi, v);
  ld4(v, c3+b); pack_store(g_c3h,g_c3l,bi, v);
}

// ----------------------------- per-node elementwise (split 2-way) -----------------------------
__global__ void k_node(const float* __restrict__ h1, const float* __restrict__ h2,
                       const float* __restrict__ h3, const float* __restrict__ c1,
                       const float* __restrict__ c2, const float* __restrict__ c3,
                       const float* __restrict__ del_t, const float* __restrict__ dptr){
  int nd = (blockIdx.x*blockDim.x + threadIdx.x) >> 5;
  if(nd >= NN) return;
  int l = threadIdx.x & 31;
  int b = nd*128 + l*4;

  if(blockIdx.y == 0){
    // ================= h-branches =================
    float s1[4];
    {
      ld4(s1, g_Yup1+b);
      float nt = sqrtf(wdot<4>(s1,s1)+1e-15f);
      float me = fminf(ftanh(nt), PMF);
      float sc = __fdividef(me, nt);
      #pragma unroll
      for(int i=0;i<4;i++) s1[i] = fsig(s1[i]*sc);
      float ns = sqrtf(wdot<4>(s1,s1)+1e-15f);
      float sl = __fdividef(fatanh(ns), ns);
      #pragma unroll
      for(int i=0;i<4;i++) s1[i] *= sl;
    }
    float s2[4];
    {
      ld4(s2, g_Yup2+b);
      float nt = sqrtf(wdot<4>(s2,s2)+1e-15f);
      float me = ftan(nt);
      float sc = __fdividef(me, nt);
      #pragma unroll
      for(int i=0;i<4;i++) s2[i] = fsig(s2[i]*sc);
      float ns = sqrtf(wdot<4>(s2,s2)+1e-15f);
      float sl = __fdividef(atanf(ns), ns);
      #pragma unroll
      for(int i=0;i<4;i++) s2[i] *= sl;
    }
    float s3[4]; ld4(s3, g_Yup3+b);
    #pragma unroll
    for(int i=0;i<4;i++) s3[i] = fsig(s3[i]);

    float h1v[4],h2v[4],h3v[4];
    ld4(h1v, h1+b); ld4(h2v, h2+b); ld4(h3v, h3+b);
    float nh1 = g_nh1[nd], nh2 = g_nh2[nd];
    float nh3 = sqrtf(wdot<4>(h3v,h3v)+1e-15f);

    // Poincare h-branch
    float ht1p[4], ht2p[4], ht3p[4], tmp[4];
    float m1p = pwmulp_k(s1, h1v, nh1, ht1p);
    float m2p, m3p;
    {
      float mm = fminf(ftanh(atanf(nh2)), PMF);
      float sc = __fdividef(mm, nh2);
      #pragma unroll
      for(int i=0;i<4;i++) tmp[i] = h2v[i]*sc;
      m2p = pwmulp_k(s2, tmp, mm, ht2p);
    }
    {
      float mm = fminf(ftanh(nh3), PMF);
      float sc = __fdividef(mm, nh3);
      #pragma unroll
      for(int i=0;i<4;i++) tmp[i] = h3v[i]*sc;
      m3p = pwmulp_k(s3, tmp, mm, ht3p);
    }
    {
      float la = __fdividef(2.f, 1.f-m1p*m1p);
      float lb = __fdividef(2.f, 1.f-m2p*m2p);
      float lc = __fdividef(2.f, 1.f-m3p*m3p);
      float den = fmaxf(fabsf(la+lb+lc-3.f), EPSF);
      float num[4];
      #pragma unroll
      for(int i=0;i<4;i++) num[i] = la*ht1p[i]+lb*ht2p[i]+lc*ht3p[i];
      float nnum = sqrtf(wdot<4>(num,num)+1e-15f);
      float nn = __fdividef(nnum, den);
      float m = fminf(ftanh(0.5f*fatanh(nn)), PMF);
      float sc = __fdividef(3.f*m, nnum);
      #pragma unroll
      for(int i=0;i<4;i++) num[i] *= sc;
      st4(g_h1p+b, num);
      if(l==0) g_y2p[nd] = 9.f*m*m;
    }

    // Sphere h-branch (l1 recomputed from h1: l1 = h1*fatanh(nh1)/nh1)
    float ht1s[4], ht2s[4], ht3s[4];
    float m2s;
    {
      float nl1 = fatanh(nh1);
      float mm = ftan(nl1);
      float sc = __fdividef(mm, nh1);   // h1 * mm/nh1 has norm mm
      #pragma unroll
      for(int i=0;i<4;i++) tmp[i] = h1v[i]*sc;
      float m1s = pwmulp_k(s1, tmp, mm, ht1s);
      m2s = pwmuls_k(s2, h2v, nh2, ht2s);
      float mm3 = ftan(nh3);
      float sc3 = __fdividef(mm3, nh3);
      #pragma unroll
      for(int i=0;i<4;i++) tmp[i] = h3v[i]*sc3;
      float m3s = pwmuls_k(s3, tmp, mm3, ht3s);
      float la = __fdividef(2.f, 1.f-m1s*m1s);
      float lb = __fdividef(2.f, 1.f-m2s*m2s);
      float lc = __fdividef(2.f, 1.f-m3s*m3s);
      float den = fmaxf(fabsf(la+lb+lc-3.f), EPSF);
      float num[4];
      #pragma unroll
      for(int i=0;i<4;i++) num[i] = la*ht1s[i]+lb*ht2s[i]+lc*ht3s[i];
      float nnum = sqrtf(wdot<4>(num,num)+1e-15f);
      float nn = __fdividef(nnum, den);
      float m = fminf(ftanh(0.5f*fatanh(nn)), PMF);
      float sc2 = __fdividef(3.f*m, nnum);
      #pragma unroll
      for(int i=0;i<4;i++) num[i] *= sc2;
      st4(g_h1s+b, num);
      if(l==0) g_y2s[nd] = 9.f*m*m;
    }

    // Euclid h-branch
    {
      float e1s = __fdividef(fatanh(m1p), m1p);
      float e2s = __fdividef(atanf(m2s), m2s);
      float he[4];
      #pragma unroll
      for(int i=0;i<4;i++) he[i] = ht1p[i]*e1s + ht2s[i]*e2s + s3[i]*h3v[i];
      st4(g_h1e+b, he);
    }
  } else {
    // ================= cell paths =================
    float g = __fdividef(dptr[0], del_t[nd] + 1.f);
    float nx2 = sqrtf(g*g + 1e-15f);
    float ax2 = fatanh(nx2);
    float sx2 = atanf(nx2);

    // Poincare cell
    {
      float c1v[4]; ld4(c1v, c1+b);
      float cw[4]; ld4(cw, g_Ywc1+b);
      float nw = sqrtf(wdot<4>(cw,cw)+1e-15f);
      {
        float sc = __fdividef(fatanh(fminf(ftanh(nw),PMF)), nw);
        #pragma unroll
        for(int i=0;i<4;i++) cw[i] = ftanh(cw[i]*sc);
      }
      float nck = sqrtf(wdot<4>(cw,cw)+1e-15f);
      float mk = fminf(ftanh(nck), PMF);
      {
        float sc = __fdividef(mk, nck);
        #pragma unroll
        for(int i=0;i<4;i++) cw[i] *= sc;
      }
      float x2 = mk*mk;
      float y2 = wdot<4>(c1v,c1v);
      float xys = 0.f;
      #pragma unroll
      for(int i=0;i<4;i++) xys -= cw[i]*c1v[i];
      float xy = wred(xys);
      float cx = 1.f+2.f*xy+y2, cy = 1.f-x2;
      float idn = __fdividef(1.f, safe_den(1.f+2.f*xy+x2*y2));
      float t1[4];
      #pragma unroll
      for(int i=0;i<4;i++) t1[i] = (cx*(-cw[i]) + cy*c1v[i])*idn;
      float n2t1 = fmaxf((cx*cx*x2 + 2.f*cx*cy*xy + cy*cy*y2)*idn*idn, 0.f);
      if(n2t1 > PMF*PMF){
        float sc = PMF*rsqrtf(n2t1);
        #pragma unroll
        for(int i=0;i<4;i++) t1[i] *= sc;
        n2t1 = PMF*PMF;
      }
      float m2 = fminf(ftanh(__fdividef(g*mk, nx2)*ax2), PMF);
      float t2s = __fdividef(m2, mk);
      float xys2 = 0.f;
      #pragma unroll
      for(int i=0;i<4;i++) xys2 += t1[i]*cw[i]*t2s;
      float xy2 = wred(xys2);
      x2 = n2t1; y2 = m2*m2;
      cx = 1.f+2.f*xy2+y2; cy = 1.f-x2;
      idn = __fdividef(1.f, safe_den(1.f+2.f*xy2+x2*y2));
      float ck[4];
      #pragma unroll
      for(int i=0;i<4;i++) ck[i] = (cx*t1[i] + cy*cw[i]*t2s)*idn;
      float n2ck = fmaxf((cx*cx*x2 + 2.f*cx*cy*xy2 + cy*cy*y2)*idn*idn, 0.f);
      float nckt = sqrtf(n2ck + 1e-15f);
      if(nckt > PMF){
        float sc = __fdividef(PMF, nckt);
        #pragma unroll
        for(int i=0;i<4;i++) ck[i] *= sc;
        nckt = PMF;
      }
      float fp[4]; ld4(fp, g_Yuf1+b);
      float nf = sqrtf(wdot<4>(fp,fp)+1e-15f);
      float scf = __fdividef(fatanh(fminf(ftanh(nf),PMF)), nf);
      #pragma unroll
      for(int i=0;i<4;i++) fp[i] = fsig(fp[i]*scf);
      float P1[4];
      float mP1 = pwmulp_k(fp, ck, nckt, P1);
      st4(g_P1+b, P1);
      if(l==0) g_lam1[nd] = __fdividef(2.f, 1.f-mP1*mP1);
    }

    // Sphere cell
    {
      float c2v[4]; ld4(c2v, c2+b);
      float cw[4]; ld4(cw, g_Ywc2+b);
      float nw = sqrtf(wdot<4>(cw,cw)+1e-15f);
      {
        float sc = __fdividef(atanf(ftan(nw)), nw);
        #pragma unroll
        for(int i=0;i<4;i++) cw[i] = ftanh(cw[i]*sc);
      }
      float nck = sqrtf(wdot<4>(cw,cw)+1e-15f);
      float mk = ftan(nck);
      {
        float sc = __fdividef(mk, nck);
        #pragma unroll
        for(int i=0;i<4;i++) cw[i] *= sc;
      }
      float x2 = mk*mk;
      float y2 = wdot<4>(c2v,c2v);
      float xys = 0.f;
      #pragma unroll
      for(int i=0;i<4;i++) xys -= cw[i]*c2v[i];
      float xy = wred(xys);
      float cx = 1.f-2.f*xy-y2, cy = 1.f+x2;
      float idn = __fdividef(1.f, safe_den(1.f-2.f*xy+x2*y2));
      float t1[4];
      #pragma unroll
      for(int i=0;i<4;i++) t1[i] = (cx*(-cw[i]) + cy*c2v[i])*idn;
      float n2t1 = fmaxf((cx*cx*x2 + 2.f*cx*cy*xy + cy*cy*y2)*idn*idn, 0.f);
      float m2 = ftan(__fdividef(g*mk, nx2)*sx2);
      float t2s = __fdividef(m2, mk);
      float xys2 = 0.f;
      #pragma unroll
      for(int i=0;i<4;i++) xys2 += t1[i]*cw[i]*t2s;
      float xy2 = wred(xys2);
      x2 = n2t1; y2 = m2*m2;
      cx = 1.f-2.f*xy2-y2; cy = 1.f+x2;
      idn = __fdividef(1.f, safe_den(1.f-2.f*xy2+x2*y2));
      float ck[4];
      #pragma unroll
      for(int i=0;i<4;i++) ck[i] = (cx*t1[i] + cy*cw[i]*t2s)*idn;
      float n2ck = fmaxf((cx*cx*x2 + 2.f*cx*cy*xy2 + cy*cy*y2)*idn*idn, 0.f);
      float nckt = sqrtf(n2ck + 1e-15f);
      float fs[4]; ld4(fs, g_Yuf2+b);
      float nf = sqrtf(wdot<4>(fs,fs)+1e-15f);
      float scf = __fdividef(atanf(ftan(nf)), nf);
      #pragma unroll
      for(int i=0;i<4;i++) fs[i] = fsig(fs[i]*scf);
      float P2[4];
      float mP2 = pwmuls_k(fs, ck, nckt, P2);
      st4(g_P2+b, P2);
      if(l==0) g_lam2[nd] = __fdividef(2.f, 1.f+mP2*mP2);
    }

    // Euclid cell
    {
      float c3v[4]; ld4(c3v, c3+b);
      float cske[4]; ld4(cske, g_Ywc3+b);
      float fe[4]; ld4(fe, g_Yuf3+b);
      float E3[4];
      #pragma unroll
      for(int i=0;i<4;i++){
        float ck = ftanh(cske[i]);
        E3[i] = fsig(fe[i])*(c3v[i] - ck + ck*g);
      }
      st4(g_E3+b, E3);
    }
  }
}

// ----------------------------- gather + attention + cell reductions (split 3-way) -----------------------------
__global__ void k_attn(const int* __restrict__ nbr){
  int nd = (blockIdx.x*blockDim.x + threadIdx.x) >> 5;
  if(nd >= NN) return;
  int l = threadIdx.x & 31;
  int b = nd*128 + l*4;
  int bi = nd*64 + l*2;
  const int* nb = nbr + nd*8;
  int j8[8], nj[8];
  #pragma unroll
  for(int k=0;k<8;k++){ j8[k] = nb[k]; nj[k] = j8[k]*128 + l*4; }

  int sec = blockIdx.y;
  if(sec == 0){
    // ---- Poincare attention
    {
      float yq[4]; ld4(yq, g_Yq+b);
      float nq = sqrtf(wdot<4>(yq,yq) + 1e-15f);
      float mp = fminf(ftanh(nq), PMF);
      float x2 = mp*mp;
      float xq[4];
      {
        float sc = __fdividef(mp, nq);
        #pragma unroll
        for(int i=0;i<4;i++) xq[i] = yq[i]*sc;
      }
      float hk[8][4], sc[8], y2[8];
      #pragma unroll
      for(int k=0;k<8;k++){
        ld4(hk[k], g_h1p + nj[k]);
        y2[k] = g_y2p[j8[k]];
        float s = 0.f;
        #pragma unroll
        for(int i=0;i<4;i++) s -= xq[i]*hk[k][i];
        float xy = wred(s);
        float cx = 1.f + 2.f*xy + y2[k];
        float cy = 1.f - x2;
        float dn = safe_den(1.f + 2.f*xy + x2*y2[k]);
        float o2 = cx*cx*x2 + 2.f*cx*cy*xy + cy*cy*y2[k];
        float nr = fminf(__fdividef(sqrtf(fmaxf(o2,0.f) + 1e-15f), fabsf(dn)), PMF);
        sc[k] = -2.f*fatanh(nr);
      }
      softmax8(sc);
      float num[4] = {0,0,0,0};
      float ds = 0.f;
      #pragma unroll
      for(int k=0;k<8;k++){
        float lam = __fdividef(2.f, 1.f - y2[k]);
        float wk = sc[k]*lam;
        #pragma unroll
        for(int i=0;i<4;i++) num[i] += wk*hk[k][i];
        ds += sc[k]*(lam - 1.f);
      }
      float den = fmaxf(fabsf(ds), EPSF);
      float nnum = sqrtf(wdot<4>(num,num) + 1e-15f);
      float nn = __fdividef(nnum, den);
      float m = fminf(ftanh(0.5f*fatanh(nn)), PMF);
      float st = __fdividef(fatanh(m), nnum);
      #pragma unroll
      for(int i=0;i<4;i++) num[i] *= st;
      pack_store(g_A1h, g_A1l, bi, num);
    }
    // ---- Euclid cell sum
    {
      float acc[4] = {0,0,0,0};
      #pragma unroll
      for(int k=0;k<8;k++){
        float ev[4]; ld4(ev, g_E3 + nj[k]);
        #pragma unroll
        for(int i=0;i<4;i++) acc[i] += ev[i];
      }
      st4(g_c3o+b, acc);
    }
  } else if(sec == 1){
    // ---- Sphere attention
    {
      float yq[4]; ld4(yq, g_Yq+b);
      float nq = sqrtf(wdot<4>(yq,yq) + 1e-15f);
      float msp = ftan(nq);
      float x2 = msp*msp;
      float xq[4];
      {
        float sc = __fdividef(msp, nq);
        #pragma unroll
        for(int i=0;i<4;i++) xq[i] = yq[i]*sc;
      }
      float hk[8][4], sc[8], y2[8];
      #pragma unroll
      for(int k=0;k<8;k++){
        ld4(hk[k], g_h1s + nj[k]);
        y2[k] = g_y2s[j8[k]];
        float s = 0.f;
        #pragma unroll
        for(int i=0;i<4;i++) s -= xq[i]*hk[k][i];
        float xy = wred(s);
        float cx = 1.f - 2.f*xy - y2[k];
        float cy = 1.f + x2;
        float dn = safe_den(1.f - 2.f*xy + x2*y2[k]);
        float o2 = cx*cx*x2 + 2.f*cx*cy*xy + cy*cy*y2[k];
        float nr = __fdividef(sqrtf(fmaxf(o2,0.f) + 1e-15f), fabsf(dn));
        sc[k] = -2.f*atanf(nr);
      }
      softmax8(sc);
      float num[4] = {0,0,0,0};
      float ds = 0.f;
      #pragma unroll
      for(int k=0;k<8;k++){
        float lam = __fdividef(2.f, 1.f + y2[k]);
        float wk = sc[k]*lam;
        #pragma unroll
        for(int i=0;i<4;i++) num[i] += wk*hk[k][i];
        ds += sc[k]*(lam - 1.f);
      }
      float den = fmaxf(fabsf(ds), EPSF);
      float nnum = sqrtf(wdot<4>(num,num) + 1e-15f);
      float nn = __fdividef(nnum, den);
      float m = ftan(0.5f*atanf(nn));
      float st = __fdividef(atanf(m), nnum);
      #pragma unroll
      for(int i=0;i<4;i++) num[i] *= st;
      pack_store(g_A2h, g_A2l, bi, num);
    }
    // ---- Sphere cell reduction
    {
      float num[4] = {0,0,0,0};
      float ds = 0.f;
      #pragma unroll
      for(int k=0;k<8;k++){
        float pv[4]; ld4(pv, g_P2 + nj[k]);
        float lam = g_lam2[j8[k]];
        #pragma unroll
        for(int i=0;i<4;i++) num[i] += lam*pv[i];
        ds += lam - 1.f;
      }
      float den = fmaxf(fabsf(ds), EPSF);
      float nnum = sqrtf(wdot<4>(num,num) + 1e-15f);
      float nn = __fdividef(nnum, den);
      float m = ftan(0.5f*atanf(nn));
      float st = __fdividef(m, nnum);
      #pragma unroll
      for(int i=0;i<4;i++) num[i] *= st;
      st4(g_c2o+b, num);
      if(l==0) g_n2c2o[nd] = m*m;
    }
  } else {
    // ---- Euclid attention
    {
      float yq[4]; ld4(yq, g_Yq+b);
      const float isq = 0.08838834764831845f;
      float hk[8][4], sc[8];
      #pragma unroll
      for(int k=0;k<8;k++){
        ld4(hk[k], g_h1e + nj[k]);
        sc[k] = wdot<4>(hk[k], yq) * isq;
      }
      softmax8(sc);
      float num[4] = {0,0,0,0};
      #pragma unroll
      for(int k=0;k<8;k++){
        #pragma unroll
        for(int i=0;i<4;i++) num[i] += sc[k]*hk[k][i];
      }
      pack_store(g_A3h, g_A3l, bi, num);
    }
    // ---- Poincare cell reduction
    {
      float num[4] = {0,0,0,0};
      float ds = 0.f;
      #pragma unroll
      for(int k=0;k<8;k++){
        float pv[4]; ld4(pv, g_P1 + nj[k]);
        float lam = g_lam1[j8[k]];
        #pragma unroll
        for(int i=0;i<4;i++) num[i] += lam*pv[i];
        ds += lam - 1.f;
      }
      float den = fmaxf(fabsf(ds), EPSF);
      float nnum = sqrtf(wdot<4>(num,num) + 1e-15f);
      float nn = __fdividef(nnum, den);
      float m = fminf(ftanh(0.5f*fatanh(nn)), PMF);
      float st = __fdividef(m, nnum);
      #pragma unroll
      for(int i=0;i<4;i++) num[i] *= st;
      st4(g_c1o+b, num);
      if(l==0) g_n2c1o[nd] = m*m;
    }
  }
}

// ----------------------------- final epilogue -----------------------------
__global__ void k_final(const float* __restrict__ iou1, const float* __restrict__ iou2,
                        const float* __restrict__ iou3, float* __restrict__ out){
  int nd = (blockIdx.x*blockDim.x + threadIdx.x) >> 5;
  if(nd >= NN) return;
  int l = threadIdx.x & 31;
  int b = nd*128 + l*4;
  int b3 = nd*384 + l*4;

  // ---- Poincare
  {
    float z[12], io[12];
    #pragma unroll
    for(int c=0;c<3;c++){ ld4(z+4*c, g_Z1 + b3 + 128*c); ld4(io+4*c, iou1 + b3 + 128*c); }
    float nz = sqrtf(wdot<12>(z,z)+1e-15f);
    float mz = fminf(ftanh(nz), PMF);
    {
      float sc = __fdividef(mz, nz);
      #pragma unroll
      for(int i=0;i<12;i++) z[i] *= sc;
    }
    float x2 = wdot<12>(io,io);
    float xy = wdot<12>(io,z);
    float y2 = mz*mz;
    float cx = 1.f+2.f*xy+y2, cy = 1.f-x2;
    float idn = __fdividef(1.f, safe_den(1.f+2.f*xy+x2*y2));
    float ni[12];
    #pragma unroll
    for(int i=0;i<12;i++) ni[i] = (cx*io[i] + cy*z[i])*idn;
    float n2ni = fmaxf((cx*cx*x2 + 2.f*cx*cy*xy + cy*cy*y2)*idn*idn, 0.f);
    if(n2ni > PMF*PMF){
      float sc = PMF*rsqrtf(n2ni);
      #pragma unroll
      for(int i=0;i<12;i++) ni[i] *= sc;
    }
    float ip[4], op[4], up[4];
    {
      float n0 = sqrtf(wdot<4>(ni,ni)+1e-15f);
      float s0 = __fdividef(fatanh(n0), n0);
      float n1 = sqrtf(wdot<4>(ni+4,ni+4)+1e-15f);
      float s1 = __fdividef(fatanh(n1), n1);
      float n2 = sqrtf(wdot<4>(ni+8,ni+8)+1e-15f);
      float s2 = __fdividef(fatanh(n2), n2);
      #pragma unroll
      for(int i=0;i<4;i++){
        ip[i] = fsig(ni[i]*s0);
        op[i] = fsig(ni[4+i]*s1);
        up[i] = ftanh(ni[8+i]*s2);
      }
    }
    float nup = sqrtf(wdot<4>(up,up)+1e-15f);
    float t[4];
    float mt = pwmulp_k(ip, up, nup, t);
    float cc[4]; ld4(cc, g_c1o+b);
    float y2c = g_n2c1o[nd];
    float xys = 0.f;
    #pragma unroll
    for(int i=0;i<4;i++) xys += t[i]*cc[i];
    float xyc = wred(xys);
    float x2c = mt*mt;
    float cxc = 1.f+2.f*xyc+y2c, cyc = 1.f-x2c;
    float idnc = __fdividef(1.f, safe_den(1.f+2.f*xyc+x2c*y2c));
    float nc[4];
    #pragma unroll
    for(int i=0;i<4;i++) nc[i] = (cxc*t[i] + cyc*cc[i])*idnc;
    float n2nc = fmaxf((cxc*cxc*x2c + 2.f*cxc*cyc*xyc + cyc*cyc*y2c)*idnc*idnc, 0.f);
    float nnc = sqrtf(n2nc + 1e-15f);
    if(nnc > PMF){
      float sc = __fdividef(PMF, nnc);
      #pragma unroll
      for(int i=0;i<4;i++) nc[i] *= sc;
      nnc = PMF;
    }
    float lt[4];
    {
      float sc = __fdividef(fatanh(nnc), nnc);
      #pragma unroll
      for(int i=0;i<4;i++) lt[i] = ftanh(nc[i]*sc);
    }
    float nlt = sqrtf(wdot<4>(lt,lt)+1e-15f);
    float nh[4];
    pwmulp_k(op, lt, nlt, nh);
    st4(out + 0*NN*128 + b, nh);
    st4(out + 1*NN*128 + b, nc);
  }

  // ---- Sphere
  {
    float z[12], io[12];
    #pragma unroll
    for(int c=0;c<3;c++){ ld4(z+4*c, g_Z2 + b3 + 128*c); ld4(io+4*c, iou2 + b3 + 128*c); }
    float nz = sqrtf(wdot<12>(z,z)+1e-15f);
    float mz = ftan(nz);
    {
      float sc = __fdividef(mz, nz);
      #pragma unroll
      for(int i=0;i<12;i++) z[i] *= sc;
    }
    float x2 = wdot<12>(io,io);
    float xy = wdot<12>(io,z);
    float y2 = mz*mz;
    float cx = 1.f-2.f*xy-y2, cy = 1.f+x2;
    float idn = __fdividef(1.f, safe_den(1.f-2.f*xy+x2*y2));
    float ni[12];
    #pragma unroll
    for(int i=0;i<12;i++) ni[i] = (cx*io[i] + cy*z[i])*idn;
    float ip[4], op[4], up[4];
    {
      float n0 = sqrtf(wdot<4>(ni,ni)+1e-15f);
      float s0 = __fdividef(atanf(n0), n0);
      float n1 = sqrtf(wdot<4>(ni+4,ni+4)+1e-15f);
      float s1 = __fdividef(atanf(n1), n1);
      float n2 = sqrtf(wdot<4>(ni+8,ni+8)+1e-15f);
      float s2 = __fdividef(atanf(n2), n2);
      #pragma unroll
      for(int i=0;i<4;i++){
        ip[i] = fsig(ni[i]*s0);
        op[i] = fsig(ni[4+i]*s1);
        up[i] = ftanh(ni[8+i]*s2);
      }
    }
    float nup = sqrtf(wdot<4>(up,up)+1e-15f);
    float t[4];
    float mt = pwmuls_k(ip, up, nup, t);
    float cc[4]; ld4(cc, g_c2o+b);
    float y2c = g_n2c2o[nd];
    float xys = 0.f;
    #pragma unroll
    for(int i=0;i<4;i++) xys += t[i]*cc[i];
    float xyc = wred(xys);
    float x2c = mt*mt;
    float cxc = 1.f-2.f*xyc-y2c, cyc = 1.f+x2c;
    float idnc = __fdividef(1.f, safe_den(1.f-2.f*xyc+x2c*y2c));
    float nc[4];
    #pragma unroll
    for(int i=0;i<4;i++) nc[i] = (cxc*t[i] + cyc*cc[i])*idnc;
    float n2nc = fmaxf((cxc*cxc*x2c + 2.f*cxc*cyc*xyc + cyc*cyc*y2c)*idnc*idnc, 0.f);
    float nnc = sqrtf(n2nc + 1e-15f);
    float lt[4];
    {
      float sc = __fdividef(atanf(nnc), nnc);
      #pragma unroll
      for(int i=0;i<4;i++) lt[i] = ftanh(nc[i]*sc);
    }
    float nlt = sqrtf(wdot<4>(lt,lt)+1e-15f);
    float nh[4];
    pwmuls_k(op, lt, nlt, nh);
    st4(out + 2*NN*128 + b, nh);
    st4(out + 3*NN*128 + b, nc);
  }

  // ---- Euclid
  {
    float z[12], io[12];
    #pragma unroll
    for(int c=0;c<3;c++){ ld4(z+4*c, g_Z3 + b3 + 128*c); ld4(io+4*c, iou3 + b3 + 128*c); }
    float cc[4]; ld4(cc, g_c3o+b);
    float nc[4], nh[4];
    #pragma unroll
    for(int i=0;i<4;i++){
      float ip = fsig(io[i]   + z[i]);
      float op = fsig(io[4+i] + z[4+i]);
      float up = ftanh(io[8+i] + z[8+i]);
      nc[i] = ip*up + cc[i];
      nh[i] = op*ftanh(nc[i]);
    }
    st4(out + 4*NN*128 + b, nh);
    st4(out + 5*NN*128 + b, nc);
  }
}

// ----------------------------- launch -----------------------------
extern "C" void kernel_launch(void* const* d_in, const int* in_sizes, int n_in,
                              void* d_out, int out_size){
  const float* x     = (const float*)d_in[0];
  const float* h1    = (const float*)d_in[1];
  const float* c1    = (const float*)d_in[2];
  const float* h2    = (const float*)d_in[3];
  const float* c2    = (const float*)d_in[4];
  const float* h3    = (const float*)d_in[5];
  const float* c3    = (const float*)d_in[6];
  const float* del_t = (const float*)d_in[7];
  const float* iou1  = (const float*)d_in[8];
  const float* iou2  = (const float*)d_in[9];
  const float* iou3  = (const float*)d_in[10];
  const float* Wq_w  = (const float*)d_in[11];
  const float* Wq_b  = (const float*)d_in[12];
  const float* Wc_w  = (const float*)d_in[13];
  const float* Wc_b  = (const float*)d_in[14];
  const float* Uf_w  = (const float*)d_in[15];
  const float* Uf_b  = (const float*)d_in[16];
  const float* Up_w  = (const float*)d_in[17];
  const float* Up_b  = (const float*)d_in[18];
  const float* Uiou_w= (const float*)d_in[19];
  const float* Uiou_b= (const float*)d_in[20];
  const float* dptr  = (const float*)d_in[21];
  const int*   nbr   = (const int*)d_in[22];
  float* out = (float*)d_out;

  cudaFuncSetAttribute(k_gemm1, cudaFuncAttributeMaxDynamicSharedMemorySize, GSMEM);
  cudaFuncSetAttribute(k_gemm2, cudaFuncAttributeMaxDynamicSharedMemorySize, GSMEM);

  k_prep<<<NN/8 + 224, 256>>>(h1, h2, c1, c2, x, h3, c3, Wq_w, Wc_w, Uf_w, Up_w, Uiou_w);
  k_gemm1<<<dim3(NN/64, 1, 10), 256, GSMEM>>>(Wq_b, Wc_b, Uf_b, Up_b);
  k_node<<<dim3(NN/8, 2), 256>>>(h1, h2, h3, c1, c2, c3, del_t, dptr);
  k_attn<<<dim3(NN/8, 3), 256>>>(nbr);
  k_gemm2<<<dim3(NN/64, 3, 3), 256, GSMEM>>>(Uiou_b);
  k_final<<<NN/8, 256>>>(iou1, iou2, iou3, out);
}